// round 1
// baseline (speedup 1.0000x reference)
#include <cuda_runtime.h>
#include <mma.h>
#include <math.h>

using namespace nvcuda;

#define Bsz 512
#define Lsz 128
#define Dsz 512
#define Hn  8
#define HDsz 64
#define LN_EPS 1e-5f

// Scratch (static device globals -- allocation-guard safe)
__device__ float g_qkv[Bsz * Lsz * 3 * Dsz];   // (B, L, 1536)  ~403MB
__device__ float g_o[Bsz * Lsz * Dsz];         // (B, L, 512)   ~134MB
__device__ float g_h[Bsz * Lsz * Dsz];         // (B, L, 512)   ~134MB

// ---------------------------------------------------------------------------
// GEMM: C[m,n] = sum_k A[m,k] * W[n,k] + bias[n] (+ Cadd[m,n])
// A: (M,K) row-major fp32, W: (N,K) row-major fp32 (i.e. C = A @ W^T)
// tf32 WMMA, 64x64 block tile, BK=32, 8 warps (256 threads).
// M,N,K must be multiples of 64/64/32 (they are: 65536, {1536,512}, 512).
// ---------------------------------------------------------------------------
template <bool ADDC>
__global__ void gemm_tf32(const float* __restrict__ A, const float* __restrict__ W,
                          const float* __restrict__ bias, const float* __restrict__ Cadd,
                          float* __restrict__ C, int M, int N, int K)
{
    constexpr int BM = 64, BN = 64, BK = 32;
    constexpr int LDT = 36;   // tile ld (pad), 36*4B = 144B (16B aligned rows)
    constexpr int LDO = 68;   // epilogue ld

    __shared__ float sA[BM * LDT];
    __shared__ float sW[BN * LDT];
    __shared__ float sOut[BM * LDO];

    const int t   = threadIdx.x;
    const int wid = t >> 5;
    const int bm  = blockIdx.y * BM;
    const int bn  = blockIdx.x * BN;
    const int wr  = wid & 3;     // warp row (16 rows each)
    const int wc  = wid >> 2;    // warp col (32 cols each -> 2 frags)

    wmma::fragment<wmma::accumulator, 16, 16, 8, float> cfr[2];
    wmma::fill_fragment(cfr[0], 0.0f);
    wmma::fill_fragment(cfr[1], 0.0f);

    const int lrow = t >> 2;          // 0..63
    const int lq   = (t & 3) * 8;     // 0,8,16,24

    for (int k0 = 0; k0 < K; k0 += BK) {
        const float* ap = A + (size_t)(bm + lrow) * K + k0 + lq;
        const float* wp = W + (size_t)(bn + lrow) * K + k0 + lq;
        float4 a0 = *(const float4*)(ap);
        float4 a1 = *(const float4*)(ap + 4);
        float4 w0 = *(const float4*)(wp);
        float4 w1 = *(const float4*)(wp + 4);

        float* sa = &sA[lrow * LDT + lq];
        sa[0] = wmma::__float_to_tf32(a0.x); sa[1] = wmma::__float_to_tf32(a0.y);
        sa[2] = wmma::__float_to_tf32(a0.z); sa[3] = wmma::__float_to_tf32(a0.w);
        sa[4] = wmma::__float_to_tf32(a1.x); sa[5] = wmma::__float_to_tf32(a1.y);
        sa[6] = wmma::__float_to_tf32(a1.z); sa[7] = wmma::__float_to_tf32(a1.w);

        float* sw = &sW[lrow * LDT + lq];
        sw[0] = wmma::__float_to_tf32(w0.x); sw[1] = wmma::__float_to_tf32(w0.y);
        sw[2] = wmma::__float_to_tf32(w0.z); sw[3] = wmma::__float_to_tf32(w0.w);
        sw[4] = wmma::__float_to_tf32(w1.x); sw[5] = wmma::__float_to_tf32(w1.y);
        sw[6] = wmma::__float_to_tf32(w1.z); sw[7] = wmma::__float_to_tf32(w1.w);

        __syncthreads();

        #pragma unroll
        for (int kk = 0; kk < BK; kk += 8) {
            wmma::fragment<wmma::matrix_a, 16, 16, 8, wmma::precision::tf32, wmma::row_major> af;
            wmma::load_matrix_sync(af, &sA[(wr * 16) * LDT + kk], LDT);
            #pragma unroll
            for (int j = 0; j < 2; j++) {
                wmma::fragment<wmma::matrix_b, 16, 16, 8, wmma::precision::tf32, wmma::col_major> bf;
                wmma::load_matrix_sync(bf, &sW[(wc * 32 + j * 16) * LDT + kk], LDT);
                wmma::mma_sync(cfr[j], af, bf, cfr[j]);
            }
        }
        __syncthreads();
    }

    wmma::store_matrix_sync(&sOut[(wr * 16) * LDO + wc * 32],      cfr[0], LDO, wmma::mem_row_major);
    wmma::store_matrix_sync(&sOut[(wr * 16) * LDO + wc * 32 + 16], cfr[1], LDO, wmma::mem_row_major);
    __syncthreads();

    const int r  = t >> 2;          // 0..63
    const int cg = (t & 3) * 16;    // 0,16,32,48
    const size_t grow = (size_t)(bm + r) * N + bn + cg;
    #pragma unroll
    for (int u = 0; u < 4; u++) {
        float4 v = *(float4*)&sOut[r * LDO + cg + u * 4];
        const int c = bn + cg + u * 4;
        v.x += bias[c];     v.y += bias[c + 1];
        v.z += bias[c + 2]; v.w += bias[c + 3];
        if (ADDC) {
            float4 cd = *(const float4*)&Cadd[grow + u * 4];
            v.x += cd.x; v.y += cd.y; v.z += cd.z; v.w += cd.w;
        }
        *(float4*)&C[grow + u * 4] = v;
    }
}

// ---------------------------------------------------------------------------
// Attention: one block per (b, h). 256 threads (8 warps).
// S = (Q*0.125) @ K^T  (wmma tf32), softmax(S + bias) fp32, O = P @ V (wmma).
// smem: Q[128][68] + K[128][68] + V[128][68] + S[128][132]  = 172,032 B dyn.
// ---------------------------------------------------------------------------
#define ATTN_SMEM_BYTES ((3 * 128 * 68 + 128 * 132) * 4)

__global__ void attn_kernel(const float* __restrict__ qkv,
                            const float* __restrict__ corr,
                            const int*   __restrict__ mask,
                            const float* __restrict__ bscale,
                            float* __restrict__ og)
{
    extern __shared__ float sm[];
    float* sQ = sm;                   // [128][68]
    float* sK = sQ + 128 * 68;        // [128][68]
    float* sV = sK + 128 * 68;        // [128][68]
    float* sS = sV + 128 * 68;        // [128][132]
    __shared__ float sB[128];

    const int bh = blockIdx.x;
    const int b  = bh >> 3;
    const int h  = bh & 7;
    const int t  = threadIdx.x;
    const int wid = t >> 5;

    // ---- load Q (scaled), K, V into smem as tf32 ----
    {
        const int row  = t >> 1;          // 0..127
        const int half = (t & 1) * 32;    // 0 or 32
        const size_t base = (size_t)(b * Lsz + row) * (3 * Dsz) + h * HDsz + half;
        const float* qp = qkv + base;
        const float* kp = qkv + base + Dsz;
        const float* vp = qkv + base + 2 * Dsz;
        float* dq = &sQ[row * 68 + half];
        float* dk = &sK[row * 68 + half];
        float* dv = &sV[row * 68 + half];
        #pragma unroll
        for (int u = 0; u < 8; u++) {
            float4 q4 = *(const float4*)(qp + u * 4);
            float4 k4 = *(const float4*)(kp + u * 4);
            float4 v4 = *(const float4*)(vp + u * 4);
            dq[u*4+0] = wmma::__float_to_tf32(q4.x * 0.125f);
            dq[u*4+1] = wmma::__float_to_tf32(q4.y * 0.125f);
            dq[u*4+2] = wmma::__float_to_tf32(q4.z * 0.125f);
            dq[u*4+3] = wmma::__float_to_tf32(q4.w * 0.125f);
            dk[u*4+0] = wmma::__float_to_tf32(k4.x);
            dk[u*4+1] = wmma::__float_to_tf32(k4.y);
            dk[u*4+2] = wmma::__float_to_tf32(k4.z);
            dk[u*4+3] = wmma::__float_to_tf32(k4.w);
            dv[u*4+0] = wmma::__float_to_tf32(v4.x);
            dv[u*4+1] = wmma::__float_to_tf32(v4.y);
            dv[u*4+2] = wmma::__float_to_tf32(v4.z);
            dv[u*4+3] = wmma::__float_to_tf32(v4.w);
        }
        if (t < 128) {
            const float bsc = bscale[0];
            sB[t] = mask[b * Lsz + t] ? -1e30f : bsc * corr[b * Lsz + t];
        }
    }
    __syncthreads();

    // ---- S = Q @ K^T : warp grid 4x2, each warp 32x64 ----
    {
        const int wr = wid & 3, wc = wid >> 2;
        const int r0 = wr * 32, c0 = wc * 64;
        wmma::fragment<wmma::accumulator, 16, 16, 8, float> acc[2][4];
        #pragma unroll
        for (int i = 0; i < 2; i++)
            #pragma unroll
            for (int j = 0; j < 4; j++)
                wmma::fill_fragment(acc[i][j], 0.0f);

        #pragma unroll
        for (int kk = 0; kk < 64; kk += 8) {
            wmma::fragment<wmma::matrix_a, 16, 16, 8, wmma::precision::tf32, wmma::row_major> af[2];
            wmma::load_matrix_sync(af[0], &sQ[(r0 +  0) * 68 + kk], 68);
            wmma::load_matrix_sync(af[1], &sQ[(r0 + 16) * 68 + kk], 68);
            #pragma unroll
            for (int j = 0; j < 4; j++) {
                wmma::fragment<wmma::matrix_b, 16, 16, 8, wmma::precision::tf32, wmma::col_major> bf;
                wmma::load_matrix_sync(bf, &sK[(c0 + j * 16) * 68 + kk], 68);
                wmma::mma_sync(acc[0][j], af[0], bf, acc[0][j]);
                wmma::mma_sync(acc[1][j], af[1], bf, acc[1][j]);
            }
        }
        #pragma unroll
        for (int i = 0; i < 2; i++)
            #pragma unroll
            for (int j = 0; j < 4; j++)
                wmma::store_matrix_sync(&sS[(r0 + i * 16) * 132 + c0 + j * 16],
                                        acc[i][j], 132, wmma::mem_row_major);
    }
    __syncthreads();

    // ---- softmax over rows (threads 0..127, one row each), write tf32 ----
    if (t < 128) {
        float* row = &sS[t * 132];
        float m = -1e30f;
        for (int j = 0; j < 128; j++) m = fmaxf(m, row[j] + sB[j]);
        float s = 0.0f;
        for (int j = 0; j < 128; j++) {
            float e = __expf(row[j] + sB[j] - m);
            row[j] = e;
            s += e;
        }
        const float inv = 1.0f / s;
        for (int j = 0; j < 128; j++)
            row[j] = wmma::__float_to_tf32(row[j] * inv);
    }
    __syncthreads();

    // ---- O = P @ V : each warp 16 rows x 64 cols ----
    {
        const int r0 = wid * 16;
        wmma::fragment<wmma::accumulator, 16, 16, 8, float> acc[4];
        #pragma unroll
        for (int c = 0; c < 4; c++) wmma::fill_fragment(acc[c], 0.0f);

        #pragma unroll
        for (int j = 0; j < 128; j += 8) {
            wmma::fragment<wmma::matrix_a, 16, 16, 8, wmma::precision::tf32, wmma::row_major> af;
            wmma::load_matrix_sync(af, &sS[r0 * 132 + j], 132);
            #pragma unroll
            for (int c = 0; c < 4; c++) {
                wmma::fragment<wmma::matrix_b, 16, 16, 8, wmma::precision::tf32, wmma::row_major> bf;
                wmma::load_matrix_sync(bf, &sV[j * 68 + c * 16], 68);
                wmma::mma_sync(acc[c], af, bf, acc[c]);
            }
        }
        #pragma unroll
        for (int c = 0; c < 4; c++) {
            float* dst = og + ((size_t)(b * Lsz + r0)) * Dsz + h * HDsz + c * 16;
            wmma::store_matrix_sync(dst, acc[c], Dsz, wmma::mem_row_major);
        }
    }
}

// ---------------------------------------------------------------------------
// LayerNorm: one block (128 threads) per row of 512.
// ---------------------------------------------------------------------------
__global__ void ln_kernel(const float* __restrict__ hbuf,
                          const float* __restrict__ lw,
                          const float* __restrict__ lb,
                          float* __restrict__ out)
{
    __shared__ float red[8];
    const int row  = blockIdx.x;
    const int t    = threadIdx.x;   // 0..127
    const int lane = t & 31;
    const int wid  = t >> 5;

    const size_t off = (size_t)row * Dsz + t * 4;
    float4 v = *(const float4*)&hbuf[off];
    float s  = v.x + v.y + v.z + v.w;
    float s2 = v.x*v.x + v.y*v.y + v.z*v.z + v.w*v.w;

    #pragma unroll
    for (int o = 16; o > 0; o >>= 1) {
        s  += __shfl_down_sync(0xffffffffu, s,  o);
        s2 += __shfl_down_sync(0xffffffffu, s2, o);
    }
    if (lane == 0) { red[wid] = s; red[4 + wid] = s2; }
    __syncthreads();
    s  = red[0] + red[1] + red[2] + red[3];
    s2 = red[4] + red[5] + red[6] + red[7];

    const float mu  = s * (1.0f / Dsz);
    const float var = s2 * (1.0f / Dsz) - mu * mu;
    const float inv = rsqrtf(var + LN_EPS);

    float4 w4 = *(const float4*)&lw[t * 4];
    float4 b4 = *(const float4*)&lb[t * 4];
    float4 r;
    r.x = (v.x - mu) * inv * w4.x + b4.x;
    r.y = (v.y - mu) * inv * w4.y + b4.y;
    r.z = (v.z - mu) * inv * w4.z + b4.z;
    r.w = (v.w - mu) * inv * w4.w + b4.w;
    *(float4*)&out[off] = r;
}

// ---------------------------------------------------------------------------
extern "C" void kernel_launch(void* const* d_in, const int* in_sizes, int n_in,
                              void* d_out, int out_size)
{
    const float* x      = (const float*)d_in[0];
    const float* corr   = (const float*)d_in[1];
    const int*   mask   = (const int*)  d_in[2];
    const float* in_w   = (const float*)d_in[3];
    const float* in_b   = (const float*)d_in[4];
    const float* out_w  = (const float*)d_in[5];
    const float* out_b  = (const float*)d_in[6];
    const float* ln_w   = (const float*)d_in[7];
    const float* ln_b   = (const float*)d_in[8];
    const float* bscale = (const float*)d_in[9];
    float* out = (float*)d_out;

    float *qkv, *o, *h;
    cudaGetSymbolAddress((void**)&qkv, g_qkv);
    cudaGetSymbolAddress((void**)&o,   g_o);
    cudaGetSymbolAddress((void**)&h,   g_h);

    const int M = Bsz * Lsz;   // 65536

    // 1) QKV projection: (65536, 1536) = x @ in_proj_w^T + in_proj_b
    gemm_tf32<false><<<dim3(3 * Dsz / 64, M / 64), 256>>>(
        x, in_w, in_b, nullptr, qkv, M, 3 * Dsz, Dsz);

    // 2) Attention per (b, h)
    cudaFuncSetAttribute(attn_kernel, cudaFuncAttributeMaxDynamicSharedMemorySize,
                         ATTN_SMEM_BYTES);
    attn_kernel<<<Bsz * Hn, 256, ATTN_SMEM_BYTES>>>(qkv, corr, mask, bscale, o);

    // 3) out_proj + bias + residual: h = x + o @ out_proj_w^T + out_proj_b
    gemm_tf32<true><<<dim3(Dsz / 64, M / 64), 256>>>(
        o, out_w, out_b, x, h, M, Dsz, Dsz);

    // 4) LayerNorm
    ln_kernel<<<M, 128>>>(h, ln_w, ln_b, out);
}

// round 3
// speedup vs baseline: 1.0498x; 1.0498x over previous
#include <cuda_runtime.h>
#include <mma.h>
#include <math.h>
#include <cstdint>

using namespace nvcuda;

#define Bsz 512
#define Lsz 128
#define Dsz 512
#define Hn  8
#define HDsz 64
#define LN_EPS 1e-5f

// Scratch (static device globals -- allocation-guard safe)
__device__ float g_qkv[Bsz * Lsz * 3 * Dsz];   // (B, L, 1536)
__device__ float g_o[Bsz * Lsz * Dsz];         // (B, L, 512)
__device__ float g_h[Bsz * Lsz * Dsz];         // (B, L, 512)

__device__ __forceinline__ void cp16(uint32_t d, const float* s) {
    asm volatile("cp.async.cg.shared.global [%0], [%1], 16;" :: "r"(d), "l"(s));
}

// ---------------------------------------------------------------------------
// Pipelined tf32 GEMM: C = A @ W^T + bias (+ Cadd)
// A:(M,K) rm, W:(N,K) rm. BM=BN=128, BK=32, 256 thr, cp.async double buffer.
// ---------------------------------------------------------------------------
#define GEMM_SMEM ((128 + 128) * 36 * 2 * 4)   // 73728 B

template <bool ADDC>
__global__ void __launch_bounds__(256, 2)
gemm_tf32(const float* __restrict__ A, const float* __restrict__ W,
          const float* __restrict__ bias, const float* __restrict__ Cadd,
          float* __restrict__ C, int M, int N, int K)
{
    constexpr int BM = 128, BN = 128, BK = 32, LDT = 36, LDO = 132;
    constexpr int STG = (BM + BN) * LDT;
    extern __shared__ float sm[];

    const int t   = threadIdx.x;
    const int wid = t >> 5;
    const int bm  = blockIdx.y * BM;
    const int bn  = blockIdx.x * BN;
    const int wr  = wid & 3;     // 4 warp-rows of 32
    const int wc  = wid >> 2;    // 2 warp-cols of 64

    const int lrow = t >> 1;          // 0..127
    const int lcol = (t & 1) * 16;    // 0 or 16 floats

    const float* gA = A + (size_t)(bm + lrow) * K + lcol;
    const float* gW = W + (size_t)(bn + lrow) * K + lcol;

    wmma::fragment<wmma::accumulator, 16, 16, 8, float> acc[2][4];
    #pragma unroll
    for (int i = 0; i < 2; i++)
        #pragma unroll
        for (int j = 0; j < 4; j++) wmma::fill_fragment(acc[i][j], 0.0f);

    auto load_tile = [&](int s, int k0) {
        uint32_t sa = (uint32_t)__cvta_generic_to_shared(sm + s * STG + lrow * LDT + lcol);
        uint32_t sw = sa + BM * LDT * 4;
        #pragma unroll
        for (int i = 0; i < 4; i++) {
            cp16(sa + i * 16, gA + k0 + i * 4);
            cp16(sw + i * 16, gW + k0 + i * 4);
        }
    };

    const int NK = K / BK;   // 16
    load_tile(0, 0);  asm volatile("cp.async.commit_group;");
    load_tile(1, BK); asm volatile("cp.async.commit_group;");

    for (int ks = 0; ks < NK; ks++) {
        if (ks < NK - 2) asm volatile("cp.async.wait_group 1;");
        else             asm volatile("cp.async.wait_group 0;");
        __syncthreads();

        const float* a = sm + (ks & 1) * STG;
        const float* w = a + BM * LDT;
        #pragma unroll
        for (int kk = 0; kk < BK; kk += 8) {
            wmma::fragment<wmma::matrix_a, 16, 16, 8, wmma::precision::tf32, wmma::row_major> af[2];
            wmma::load_matrix_sync(af[0], a + (wr * 32) * LDT + kk, LDT);
            wmma::load_matrix_sync(af[1], a + (wr * 32 + 16) * LDT + kk, LDT);
            #pragma unroll
            for (int j = 0; j < 4; j++) {
                wmma::fragment<wmma::matrix_b, 16, 16, 8, wmma::precision::tf32, wmma::col_major> bf;
                wmma::load_matrix_sync(bf, w + (wc * 64 + j * 16) * LDT + kk, LDT);
                wmma::mma_sync(acc[0][j], af[0], bf, acc[0][j]);
                wmma::mma_sync(acc[1][j], af[1], bf, acc[1][j]);
            }
        }
        __syncthreads();
        if (ks + 2 < NK) {
            load_tile(ks & 1, (ks + 2) * BK);
            asm volatile("cp.async.commit_group;");
        }
    }

    // Epilogue: frags -> smem -> coalesced float4 stores with bias (+residual)
    #pragma unroll
    for (int i = 0; i < 2; i++)
        #pragma unroll
        for (int j = 0; j < 4; j++)
            wmma::store_matrix_sync(sm + (wr * 32 + i * 16) * LDO + wc * 64 + j * 16,
                                    acc[i][j], LDO, wmma::mem_row_major);
    __syncthreads();

    const int r  = t >> 1;
    const int cb = (t & 1) * 64;
    const size_t grow = (size_t)(bm + r) * N + bn;
    #pragma unroll
    for (int u = 0; u < 16; u++) {
        const int c = cb + u * 4;
        float4 v = *(float4*)&sm[r * LDO + c];
        v.x += bias[bn + c];     v.y += bias[bn + c + 1];
        v.z += bias[bn + c + 2]; v.w += bias[bn + c + 3];
        if (ADDC) {
            float4 d = *(const float4*)&Cadd[grow + c];
            v.x += d.x; v.y += d.y; v.z += d.z; v.w += d.w;
        }
        *(float4*)&C[grow + c] = v;
    }
}

// ---------------------------------------------------------------------------
// Attention: one block per (b, h). 256 threads (8 warps).
// ---------------------------------------------------------------------------
#define ATTN_SMEM_BYTES ((3 * 128 * 68 + 128 * 132) * 4)

__global__ void attn_kernel(const float* __restrict__ qkv,
                            const float* __restrict__ corr,
                            const int*   __restrict__ mask,
                            const float* __restrict__ bscale,
                            float* __restrict__ og)
{
    extern __shared__ float sm[];
    float* sQ = sm;                   // [128][68]
    float* sK = sQ + 128 * 68;
    float* sV = sK + 128 * 68;
    float* sS = sV + 128 * 68;        // [128][132]
    __shared__ __align__(16) float sB[128];

    const int bh = blockIdx.x;
    const int b  = bh >> 3;
    const int h  = bh & 7;
    const int t  = threadIdx.x;
    const int wid  = t >> 5;
    const int lane = t & 31;

    // ---- load Q (scaled), K, V (raw fp32; HMMA tf32 truncates in HW) ----
    {
        const int row  = t >> 1;
        const int half = (t & 1) * 32;
        const size_t base = (size_t)(b * Lsz + row) * (3 * Dsz) + h * HDsz + half;
        const float* qp = qkv + base;
        const float* kp = qkv + base + Dsz;
        const float* vp = qkv + base + 2 * Dsz;
        float* dq = &sQ[row * 68 + half];
        float* dk = &sK[row * 68 + half];
        float* dv = &sV[row * 68 + half];
        #pragma unroll
        for (int u = 0; u < 8; u++) {
            float4 q4 = *(const float4*)(qp + u * 4);
            q4.x *= 0.125f; q4.y *= 0.125f; q4.z *= 0.125f; q4.w *= 0.125f;
            *(float4*)(dq + u * 4) = q4;
            *(float4*)(dk + u * 4) = *(const float4*)(kp + u * 4);
            *(float4*)(dv + u * 4) = *(const float4*)(vp + u * 4);
        }
        if (t < 128) {
            const float bsc = bscale[0];
            sB[t] = mask[b * Lsz + t] ? -1e30f : bsc * corr[b * Lsz + t];
        }
    }
    __syncthreads();

    // ---- S = Q @ K^T : warp grid 4x2, each warp 32x64 ----
    {
        const int wr = wid & 3, wc = wid >> 2;
        const int r0 = wr * 32, c0 = wc * 64;
        wmma::fragment<wmma::accumulator, 16, 16, 8, float> acc[2][4];
        #pragma unroll
        for (int i = 0; i < 2; i++)
            #pragma unroll
            for (int j = 0; j < 4; j++) wmma::fill_fragment(acc[i][j], 0.0f);

        #pragma unroll
        for (int kk = 0; kk < 64; kk += 8) {
            wmma::fragment<wmma::matrix_a, 16, 16, 8, wmma::precision::tf32, wmma::row_major> af[2];
            wmma::load_matrix_sync(af[0], &sQ[(r0 +  0) * 68 + kk], 68);
            wmma::load_matrix_sync(af[1], &sQ[(r0 + 16) * 68 + kk], 68);
            #pragma unroll
            for (int j = 0; j < 4; j++) {
                wmma::fragment<wmma::matrix_b, 16, 16, 8, wmma::precision::tf32, wmma::col_major> bf;
                wmma::load_matrix_sync(bf, &sK[(c0 + j * 16) * 68 + kk], 68);
                wmma::mma_sync(acc[0][j], af[0], bf, acc[0][j]);
                wmma::mma_sync(acc[1][j], af[1], bf, acc[1][j]);
            }
        }
        #pragma unroll
        for (int i = 0; i < 2; i++)
            #pragma unroll
            for (int j = 0; j < 4; j++)
                wmma::store_matrix_sync(&sS[(r0 + i * 16) * 132 + c0 + j * 16],
                                        acc[i][j], 132, wmma::mem_row_major);
    }
    __syncthreads();

    // ---- softmax: warp per row-group, float4 per lane, shfl reductions ----
    {
        const float4 bv = *(const float4*)&sB[lane * 4];
        #pragma unroll
        for (int rr = 0; rr < 16; rr++) {
            const int r = wid * 16 + rr;
            float4 v = *(float4*)&sS[r * 132 + lane * 4];
            v.x += bv.x; v.y += bv.y; v.z += bv.z; v.w += bv.w;
            float m = fmaxf(fmaxf(v.x, v.y), fmaxf(v.z, v.w));
            #pragma unroll
            for (int o = 16; o > 0; o >>= 1)
                m = fmaxf(m, __shfl_xor_sync(0xffffffffu, m, o));
            float4 e;
            e.x = __expf(v.x - m); e.y = __expf(v.y - m);
            e.z = __expf(v.z - m); e.w = __expf(v.w - m);
            float s = e.x + e.y + e.z + e.w;
            #pragma unroll
            for (int o = 16; o > 0; o >>= 1)
                s += __shfl_xor_sync(0xffffffffu, s, o);
            const float inv = 1.0f / s;
            e.x *= inv; e.y *= inv; e.z *= inv; e.w *= inv;
            *(float4*)&sS[r * 132 + lane * 4] = e;
        }
    }
    __syncthreads();

    // ---- O = P @ V : each warp 16 rows x 64 cols ----
    {
        const int r0 = wid * 16;
        wmma::fragment<wmma::accumulator, 16, 16, 8, float> acc[4];
        #pragma unroll
        for (int c = 0; c < 4; c++) wmma::fill_fragment(acc[c], 0.0f);

        #pragma unroll
        for (int j = 0; j < 128; j += 8) {
            wmma::fragment<wmma::matrix_a, 16, 16, 8, wmma::precision::tf32, wmma::row_major> af;
            wmma::load_matrix_sync(af, &sS[r0 * 132 + j], 132);
            #pragma unroll
            for (int c = 0; c < 4; c++) {
                wmma::fragment<wmma::matrix_b, 16, 16, 8, wmma::precision::tf32, wmma::row_major> bf;
                wmma::load_matrix_sync(bf, &sV[j * 68 + c * 16], 68);
                wmma::mma_sync(acc[c], af, bf, acc[c]);
            }
        }
        #pragma unroll
        for (int c = 0; c < 4; c++) {
            float* dst = og + ((size_t)(b * Lsz + r0)) * Dsz + h * HDsz + c * 16;
            wmma::store_matrix_sync(dst, acc[c], Dsz, wmma::mem_row_major);
        }
    }
}

// ---------------------------------------------------------------------------
// LayerNorm: one block (128 threads) per row of 512.
// ---------------------------------------------------------------------------
__global__ void ln_kernel(const float* __restrict__ hbuf,
                          const float* __restrict__ lw,
                          const float* __restrict__ lb,
                          float* __restrict__ out)
{
    __shared__ float red[8];
    const int row  = blockIdx.x;
    const int t    = threadIdx.x;
    const int lane = t & 31;
    const int wid  = t >> 5;

    const size_t off = (size_t)row * Dsz + t * 4;
    float4 v = *(const float4*)&hbuf[off];
    float s  = v.x + v.y + v.z + v.w;
    float s2 = v.x*v.x + v.y*v.y + v.z*v.z + v.w*v.w;

    #pragma unroll
    for (int o = 16; o > 0; o >>= 1) {
        s  += __shfl_down_sync(0xffffffffu, s,  o);
        s2 += __shfl_down_sync(0xffffffffu, s2, o);
    }
    if (lane == 0) { red[wid] = s; red[4 + wid] = s2; }
    __syncthreads();
    s  = red[0] + red[1] + red[2] + red[3];
    s2 = red[4] + red[5] + red[6] + red[7];

    const float mu  = s * (1.0f / Dsz);
    const float var = s2 * (1.0f / Dsz) - mu * mu;
    const float inv = rsqrtf(var + LN_EPS);

    float4 w4 = *(const float4*)&lw[t * 4];
    float4 b4 = *(const float4*)&lb[t * 4];
    float4 r;
    r.x = (v.x - mu) * inv * w4.x + b4.x;
    r.y = (v.y - mu) * inv * w4.y + b4.y;
    r.z = (v.z - mu) * inv * w4.z + b4.z;
    r.w = (v.w - mu) * inv * w4.w + b4.w;
    *(float4*)&out[off] = r;
}

// ---------------------------------------------------------------------------
extern "C" void kernel_launch(void* const* d_in, const int* in_sizes, int n_in,
                              void* d_out, int out_size)
{
    const float* x      = (const float*)d_in[0];
    const float* corr   = (const float*)d_in[1];
    const int*   mask   = (const int*)  d_in[2];
    const float* in_w   = (const float*)d_in[3];
    const float* in_b   = (const float*)d_in[4];
    const float* out_w  = (const float*)d_in[5];
    const float* out_b  = (const float*)d_in[6];
    const float* ln_w   = (const float*)d_in[7];
    const float* ln_b   = (const float*)d_in[8];
    const float* bscale = (const float*)d_in[9];
    float* out = (float*)d_out;

    float *qkv, *o, *h;
    cudaGetSymbolAddress((void**)&qkv, g_qkv);
    cudaGetSymbolAddress((void**)&o,   g_o);
    cudaGetSymbolAddress((void**)&h,   g_h);

    const int M = Bsz * Lsz;   // 65536

    cudaFuncSetAttribute(gemm_tf32<false>, cudaFuncAttributeMaxDynamicSharedMemorySize, GEMM_SMEM);
    cudaFuncSetAttribute(gemm_tf32<true>,  cudaFuncAttributeMaxDynamicSharedMemorySize, GEMM_SMEM);
    cudaFuncSetAttribute(attn_kernel, cudaFuncAttributeMaxDynamicSharedMemorySize, ATTN_SMEM_BYTES);

    // 1) QKV projection: (65536, 1536) = x @ in_proj_w^T + in_proj_b
    gemm_tf32<false><<<dim3(3 * Dsz / 128, M / 128), 256, GEMM_SMEM>>>(
        x, in_w, in_b, nullptr, qkv, M, 3 * Dsz, Dsz);

    // 2) Attention per (b, h)
    attn_kernel<<<Bsz * Hn, 256, ATTN_SMEM_BYTES>>>(qkv, corr, mask, bscale, o);

    // 3) out_proj + bias + residual
    gemm_tf32<true><<<dim3(Dsz / 128, M / 128), 256, GEMM_SMEM>>>(
        o, out_w, out_b, x, h, M, Dsz, Dsz);

    // 4) LayerNorm
    ln_kernel<<<M, 128>>>(h, ln_w, ln_b, out);
}

// round 5
// speedup vs baseline: 2.4126x; 2.2981x over previous
#include <cuda_runtime.h>
#include <mma.h>
#include <math.h>
#include <cstdint>
#include <cuda_fp16.h>

using namespace nvcuda;

#define Bsz 512
#define Lsz 128
#define Dsz 512
#define Hn  8
#define HDsz 64
#define LN_EPS 1e-5f

// Scratch (static device globals -- allocation-guard safe)
__device__ float  g_qkv[Bsz * Lsz * 3 * Dsz];    // (B, L, 1536) fp32
__device__ __half g_oh[Bsz * Lsz * Dsz];         // attention out, fp16
__device__ float  g_h[Bsz * Lsz * Dsz];          // residual+proj, fp32
__device__ __half g_xh[Bsz * Lsz * Dsz];         // x in fp16
__device__ __half g_wih[3 * Dsz * Dsz];          // in_proj_w fp16
__device__ __half g_woh[Dsz * Dsz];              // out_proj_w fp16

__device__ __forceinline__ void cp16(uint32_t d, const void* s) {
    asm volatile("cp.async.cg.shared.global [%0], [%1], 16;" :: "r"(d), "l"(s));
}

// ---------------------------------------------------------------------------
// fp32 -> fp16 conversion, 8 elems/thread
// ---------------------------------------------------------------------------
__global__ void f2h_kernel(const float* __restrict__ in, __half* __restrict__ out, int n)
{
    int i = (blockIdx.x * blockDim.x + threadIdx.x) * 8;
    if (i >= n) return;
    float4 a = *(const float4*)(in + i);
    float4 b = *(const float4*)(in + i + 4);
    __half2 h0 = __floats2half2_rn(a.x, a.y);
    __half2 h1 = __floats2half2_rn(a.z, a.w);
    __half2 h2 = __floats2half2_rn(b.x, b.y);
    __half2 h3 = __floats2half2_rn(b.z, b.w);
    uint4 pk;
    pk.x = *(uint32_t*)&h0; pk.y = *(uint32_t*)&h1;
    pk.z = *(uint32_t*)&h2; pk.w = *(uint32_t*)&h3;
    *(uint4*)(out + i) = pk;
}

// ---------------------------------------------------------------------------
// fp16 GEMM (fp32 accum): C = A @ W^T + bias (+ Cadd)
// A:(M,K) rm fp16, W:(N,K) rm fp16. BM=BN=128, BK=64, 256 thr, double buffer.
// ---------------------------------------------------------------------------
#define LDT 72                        // halfs per smem row (144B)
#define STG ((128 + 128) * LDT)       // halfs per stage
#define GEMM_SMEM (STG * 2 * 2)       // 73728 B

template <bool ADDC>
__global__ void __launch_bounds__(256, 2)
gemm_h(const __half* __restrict__ A, const __half* __restrict__ W,
       const float* __restrict__ bias, const float* __restrict__ Cadd,
       float* __restrict__ C, int M, int N, int K)
{
    constexpr int LDO = 132;
    extern __shared__ __half sh[];
    float* sf = (float*)sh;

    const int t   = threadIdx.x;
    const int wid = t >> 5;
    const int bm  = blockIdx.y * 128;
    const int bn  = blockIdx.x * 128;
    const int wr  = wid & 3;     // 4 warp-rows of 32
    const int wc  = wid >> 2;    // 2 warp-cols of 64

    const int lrow = t >> 1;          // 0..127
    const int lcol = (t & 1) * 32;    // 0 or 32 halfs

    const __half* gA = A + (size_t)(bm + lrow) * K + lcol;
    const __half* gW = W + (size_t)(bn + lrow) * K + lcol;

    wmma::fragment<wmma::accumulator, 16, 16, 16, float> acc[2][4];
    #pragma unroll
    for (int i = 0; i < 2; i++)
        #pragma unroll
        for (int j = 0; j < 4; j++) wmma::fill_fragment(acc[i][j], 0.0f);

    auto load_tile = [&](int s, int k0) {
        uint32_t sa = (uint32_t)__cvta_generic_to_shared(sh + s * STG + lrow * LDT + lcol);
        uint32_t sw = sa + 128 * LDT * 2;
        #pragma unroll
        for (int i = 0; i < 4; i++) {
            cp16(sa + i * 16, gA + k0 + i * 8);
            cp16(sw + i * 16, gW + k0 + i * 8);
        }
    };

    const int NK = K / 64;   // 8
    load_tile(0, 0);  asm volatile("cp.async.commit_group;");
    load_tile(1, 64); asm volatile("cp.async.commit_group;");

    for (int ks = 0; ks < NK; ks++) {
        if (ks < NK - 2) asm volatile("cp.async.wait_group 1;");
        else             asm volatile("cp.async.wait_group 0;");
        __syncthreads();

        const __half* a = sh + (ks & 1) * STG;
        const __half* w = a + 128 * LDT;
        #pragma unroll
        for (int kk = 0; kk < 64; kk += 16) {
            wmma::fragment<wmma::matrix_a, 16, 16, 16, __half, wmma::row_major> af[2];
            wmma::load_matrix_sync(af[0], a + (wr * 32) * LDT + kk, LDT);
            wmma::load_matrix_sync(af[1], a + (wr * 32 + 16) * LDT + kk, LDT);
            #pragma unroll
            for (int j = 0; j < 4; j++) {
                wmma::fragment<wmma::matrix_b, 16, 16, 16, __half, wmma::col_major> bf;
                wmma::load_matrix_sync(bf, w + (wc * 64 + j * 16) * LDT + kk, LDT);
                wmma::mma_sync(acc[0][j], af[0], bf, acc[0][j]);
                wmma::mma_sync(acc[1][j], af[1], bf, acc[1][j]);
            }
        }
        __syncthreads();
        if (ks + 2 < NK) {
            load_tile(ks & 1, (ks + 2) * 64);
            asm volatile("cp.async.commit_group;");
        }
    }

    // Epilogue: frags -> smem(fp32) -> coalesced float4 stores
    #pragma unroll
    for (int i = 0; i < 2; i++)
        #pragma unroll
        for (int j = 0; j < 4; j++)
            wmma::store_matrix_sync(sf + (wr * 32 + i * 16) * LDO + wc * 64 + j * 16,
                                    acc[i][j], LDO, wmma::mem_row_major);
    __syncthreads();

    const int r  = t >> 1;
    const int cb = (t & 1) * 64;
    const size_t grow = (size_t)(bm + r) * N + bn;
    #pragma unroll
    for (int u = 0; u < 16; u++) {
        const int c = cb + u * 4;
        float4 v = *(float4*)&sf[r * LDO + c];
        v.x += bias[bn + c];     v.y += bias[bn + c + 1];
        v.z += bias[bn + c + 2]; v.w += bias[bn + c + 3];
        if (ADDC) {
            float4 d = *(const float4*)&Cadd[grow + c];
            v.x += d.x; v.y += d.y; v.z += d.z; v.w += d.w;
        }
        *(float4*)&C[grow + c] = v;
    }
}

// ---------------------------------------------------------------------------
// Attention: one block per (b, h). 256 threads (8 warps). fp16 operands.
// smem layout (halfs): Q[128*72], K[128*72], V[128*72], then fp32 S[128][132].
// P (fp16, 128*136) overlays Q+K region after softmax.
// ---------------------------------------------------------------------------
#define QKV_HALFS (3 * 128 * 72)
#define ATTN_SMEM_BYTES (QKV_HALFS * 2 + 128 * 132 * 4)

__global__ void attn_kernel(const float* __restrict__ qkv,
                            const float* __restrict__ corr,
                            const int*   __restrict__ mask,
                            const float* __restrict__ bscale,
                            __half* __restrict__ og)
{
    extern __shared__ __half smh[];
    __half* sQ = smh;                    // [128][72]
    __half* sK = sQ + 128 * 72;
    __half* sV = sK + 128 * 72;
    __half* sP = smh;                    // overlay Q..K after softmax [128][136]
    float*  sS = (float*)(smh + QKV_HALFS);   // [128][132]
    __shared__ __align__(16) float sB[128];

    const int bh = blockIdx.x;
    const int b  = bh >> 3;
    const int h  = bh & 7;
    const int t  = threadIdx.x;
    const int wid  = t >> 5;
    const int lane = t & 31;

    // ---- load Q (scaled), K, V -> fp16 smem ----
    {
        const int row  = t >> 1;
        const int half = (t & 1) * 32;
        const size_t base = (size_t)(b * Lsz + row) * (3 * Dsz) + h * HDsz + half;
        const float* qp = qkv + base;
        const float* kp = qkv + base + Dsz;
        const float* vp = qkv + base + 2 * Dsz;
        __half* dq = &sQ[row * 72 + half];
        __half* dk = &sK[row * 72 + half];
        __half* dv = &sV[row * 72 + half];
        #pragma unroll
        for (int u = 0; u < 8; u++) {
            float4 q4 = *(const float4*)(qp + u * 4);
            float4 k4 = *(const float4*)(kp + u * 4);
            float4 v4 = *(const float4*)(vp + u * 4);
            __half2 qh0 = __floats2half2_rn(q4.x * 0.125f, q4.y * 0.125f);
            __half2 qh1 = __floats2half2_rn(q4.z * 0.125f, q4.w * 0.125f);
            __half2 kh0 = __floats2half2_rn(k4.x, k4.y);
            __half2 kh1 = __floats2half2_rn(k4.z, k4.w);
            __half2 vh0 = __floats2half2_rn(v4.x, v4.y);
            __half2 vh1 = __floats2half2_rn(v4.z, v4.w);
            *(__half2*)(dq + u * 4)     = qh0;
            *(__half2*)(dq + u * 4 + 2) = qh1;
            *(__half2*)(dk + u * 4)     = kh0;
            *(__half2*)(dk + u * 4 + 2) = kh1;
            *(__half2*)(dv + u * 4)     = vh0;
            *(__half2*)(dv + u * 4 + 2) = vh1;
        }
        if (t < 128) {
            const float bsc = bscale[0];
            sB[t] = mask[b * Lsz + t] ? -1e30f : bsc * corr[b * Lsz + t];
        }
    }
    __syncthreads();

    // ---- S = Q @ K^T : warp grid 4x2, each warp 32x64 ----
    {
        const int wr = wid & 3, wc = wid >> 2;
        const int r0 = wr * 32, c0 = wc * 64;
        wmma::fragment<wmma::accumulator, 16, 16, 16, float> acc[2][4];
        #pragma unroll
        for (int i = 0; i < 2; i++)
            #pragma unroll
            for (int j = 0; j < 4; j++) wmma::fill_fragment(acc[i][j], 0.0f);

        #pragma unroll
        for (int kk = 0; kk < 64; kk += 16) {
            wmma::fragment<wmma::matrix_a, 16, 16, 16, __half, wmma::row_major> af[2];
            wmma::load_matrix_sync(af[0], &sQ[(r0 +  0) * 72 + kk], 72);
            wmma::load_matrix_sync(af[1], &sQ[(r0 + 16) * 72 + kk], 72);
            #pragma unroll
            for (int j = 0; j < 4; j++) {
                wmma::fragment<wmma::matrix_b, 16, 16, 16, __half, wmma::col_major> bf;
                wmma::load_matrix_sync(bf, &sK[(c0 + j * 16) * 72 + kk], 72);
                wmma::mma_sync(acc[0][j], af[0], bf, acc[0][j]);
                wmma::mma_sync(acc[1][j], af[1], bf, acc[1][j]);
            }
        }
        #pragma unroll
        for (int i = 0; i < 2; i++)
            #pragma unroll
            for (int j = 0; j < 4; j++)
                wmma::store_matrix_sync(&sS[(r0 + i * 16) * 132 + c0 + j * 16],
                                        acc[i][j], 132, wmma::mem_row_major);
    }
    __syncthreads();

    // ---- softmax (fp32), write P as fp16 into overlay region ----
    {
        const float4 bv = *(const float4*)&sB[lane * 4];
        #pragma unroll
        for (int rr = 0; rr < 16; rr++) {
            const int r = wid * 16 + rr;
            float4 v = *(float4*)&sS[r * 132 + lane * 4];
            v.x += bv.x; v.y += bv.y; v.z += bv.z; v.w += bv.w;
            float m = fmaxf(fmaxf(v.x, v.y), fmaxf(v.z, v.w));
            #pragma unroll
            for (int o = 16; o > 0; o >>= 1)
                m = fmaxf(m, __shfl_xor_sync(0xffffffffu, m, o));
            float4 e;
            e.x = __expf(v.x - m); e.y = __expf(v.y - m);
            e.z = __expf(v.z - m); e.w = __expf(v.w - m);
            float s = e.x + e.y + e.z + e.w;
            #pragma unroll
            for (int o = 16; o > 0; o >>= 1)
                s += __shfl_xor_sync(0xffffffffu, s, o);
            const float inv = 1.0f / s;
            __half2 p0 = __floats2half2_rn(e.x * inv, e.y * inv);
            __half2 p1 = __floats2half2_rn(e.z * inv, e.w * inv);
            *(__half2*)&sP[r * 136 + lane * 4]     = p0;
            *(__half2*)&sP[r * 136 + lane * 4 + 2] = p1;
        }
    }
    __syncthreads();

    // ---- O = P @ V : each warp 16 rows x 64 cols, result -> sS -> global ----
    {
        const int r0 = wid * 16;
        wmma::fragment<wmma::accumulator, 16, 16, 16, float> acc[4];
        #pragma unroll
        for (int c = 0; c < 4; c++) wmma::fill_fragment(acc[c], 0.0f);

        #pragma unroll
        for (int j = 0; j < 128; j += 16) {
            wmma::fragment<wmma::matrix_a, 16, 16, 16, __half, wmma::row_major> af;
            wmma::load_matrix_sync(af, &sP[r0 * 136 + j], 136);
            #pragma unroll
            for (int c = 0; c < 4; c++) {
                wmma::fragment<wmma::matrix_b, 16, 16, 16, __half, wmma::row_major> bf;
                wmma::load_matrix_sync(bf, &sV[j * 72 + c * 16], 72);
                wmma::mma_sync(acc[c], af, bf, acc[c]);
            }
        }
        #pragma unroll
        for (int c = 0; c < 4; c++)
            wmma::store_matrix_sync(&sS[r0 * 132 + c * 16], acc[c], 132, wmma::mem_row_major);
    }
    __syncthreads();

    // ---- convert O to fp16, coalesced global store ----
    {
        const int row  = t >> 1;
        const int half = (t & 1) * 32;
        __half* dst = og + (size_t)(b * Lsz + row) * Dsz + h * HDsz + half;
        const float* src = &sS[row * 132 + half];
        #pragma unroll
        for (int u = 0; u < 8; u++) {
            float4 v = *(const float4*)(src + u * 4);
            __half2 h0 = __floats2half2_rn(v.x, v.y);
            __half2 h1 = __floats2half2_rn(v.z, v.w);
            *(__half2*)(dst + u * 4)     = h0;
            *(__half2*)(dst + u * 4 + 2) = h1;
        }
    }
}

// ---------------------------------------------------------------------------
// LayerNorm: one block (128 threads) per row of 512.
// ---------------------------------------------------------------------------
__global__ void ln_kernel(const float* __restrict__ hbuf,
                          const float* __restrict__ lw,
                          const float* __restrict__ lb,
                          float* __restrict__ out)
{
    __shared__ float red[8];
    const int row  = blockIdx.x;
    const int t    = threadIdx.x;
    const int lane = t & 31;
    const int wid  = t >> 5;

    const size_t off = (size_t)row * Dsz + t * 4;
    float4 v = *(const float4*)&hbuf[off];
    float s  = v.x + v.y + v.z + v.w;
    float s2 = v.x*v.x + v.y*v.y + v.z*v.z + v.w*v.w;

    #pragma unroll
    for (int o = 16; o > 0; o >>= 1) {
        s  += __shfl_down_sync(0xffffffffu, s,  o);
        s2 += __shfl_down_sync(0xffffffffu, s2, o);
    }
    if (lane == 0) { red[wid] = s; red[4 + wid] = s2; }
    __syncthreads();
    s  = red[0] + red[1] + red[2] + red[3];
    s2 = red[4] + red[5] + red[6] + red[7];

    const float mu  = s * (1.0f / Dsz);
    const float var = s2 * (1.0f / Dsz) - mu * mu;
    const float inv = rsqrtf(var + LN_EPS);

    float4 w4 = *(const float4*)&lw[t * 4];
    float4 b4 = *(const float4*)&lb[t * 4];
    float4 r;
    r.x = (v.x - mu) * inv * w4.x + b4.x;
    r.y = (v.y - mu) * inv * w4.y + b4.y;
    r.z = (v.z - mu) * inv * w4.z + b4.z;
    r.w = (v.w - mu) * inv * w4.w + b4.w;
    *(float4*)&out[off] = r;
}

// ---------------------------------------------------------------------------
extern "C" void kernel_launch(void* const* d_in, const int* in_sizes, int n_in,
                              void* d_out, int out_size)
{
    const float* x      = (const float*)d_in[0];
    const float* corr   = (const float*)d_in[1];
    const int*   mask   = (const int*)  d_in[2];
    const float* in_w   = (const float*)d_in[3];
    const float* in_b   = (const float*)d_in[4];
    const float* out_w  = (const float*)d_in[5];
    const float* out_b  = (const float*)d_in[6];
    const float* ln_w   = (const float*)d_in[7];
    const float* ln_b   = (const float*)d_in[8];
    const float* bscale = (const float*)d_in[9];
    float* out = (float*)d_out;

    float *qkv, *h;
    __half *oh, *xh, *wih, *woh;
    cudaGetSymbolAddress((void**)&qkv, g_qkv);
    cudaGetSymbolAddress((void**)&oh,  g_oh);
    cudaGetSymbolAddress((void**)&h,   g_h);
    cudaGetSymbolAddress((void**)&xh,  g_xh);
    cudaGetSymbolAddress((void**)&wih, g_wih);
    cudaGetSymbolAddress((void**)&woh, g_woh);

    const int M = Bsz * Lsz;   // 65536

    cudaFuncSetAttribute(gemm_h<false>, cudaFuncAttributeMaxDynamicSharedMemorySize, GEMM_SMEM);
    cudaFuncSetAttribute(gemm_h<true>,  cudaFuncAttributeMaxDynamicSharedMemorySize, GEMM_SMEM);
    cudaFuncSetAttribute(attn_kernel, cudaFuncAttributeMaxDynamicSharedMemorySize, ATTN_SMEM_BYTES);

    // 0) fp32 -> fp16 conversions
    f2h_kernel<<<(M * Dsz / 8 + 255) / 256, 256>>>(x, xh, M * Dsz);
    f2h_kernel<<<(3 * Dsz * Dsz / 8 + 255) / 256, 256>>>(in_w, wih, 3 * Dsz * Dsz);
    f2h_kernel<<<(Dsz * Dsz / 8 + 255) / 256, 256>>>(out_w, woh, Dsz * Dsz);

    // 1) QKV projection
    gemm_h<false><<<dim3(3 * Dsz / 128, M / 128), 256, GEMM_SMEM>>>(
        xh, wih, in_b, nullptr, qkv, M, 3 * Dsz, Dsz);

    // 2) Attention per (b, h)
    attn_kernel<<<Bsz * Hn, 256, ATTN_SMEM_BYTES>>>(qkv, corr, mask, bscale, oh);

    // 3) out_proj + bias + residual
    gemm_h<true><<<dim3(Dsz / 128, M / 128), 256, GEMM_SMEM>>>(
        oh, woh, out_b, x, h, M, Dsz, Dsz);

    // 4) LayerNorm
    ln_kernel<<<M, 128>>>(h, ln_w, ln_b, out);
}

// round 6
// speedup vs baseline: 2.6995x; 1.1189x over previous
#include <cuda_runtime.h>
#include <mma.h>
#include <math.h>
#include <cstdint>
#include <cuda_fp16.h>

using namespace nvcuda;

#define Bsz 512
#define Lsz 128
#define Dsz 512
#define Hn  8
#define HDsz 64
#define LN_EPS 1e-5f

// Scratch (static device globals -- allocation-guard safe)
__device__ float  g_qkv[Bsz * Lsz * 3 * Dsz];    // (B, L, 1536) fp32
__device__ __half g_oh[Bsz * Lsz * Dsz];         // attention out, fp16
__device__ float  g_h[Bsz * Lsz * Dsz];          // residual+proj, fp32
__device__ __half g_xh[Bsz * Lsz * Dsz];         // x in fp16
__device__ __half g_wih[3 * Dsz * Dsz];          // in_proj_w fp16
__device__ __half g_woh[Dsz * Dsz];              // out_proj_w fp16

__device__ __forceinline__ void cp16(uint32_t d, const void* s) {
    asm volatile("cp.async.cg.shared.global [%0], [%1], 16;" :: "r"(d), "l"(s));
}

// ---------------------------------------------------------------------------
// fp32 -> fp16 conversion, 8 elems/thread
// ---------------------------------------------------------------------------
__global__ void f2h_kernel(const float* __restrict__ in, __half* __restrict__ out, int n)
{
    int i = (blockIdx.x * blockDim.x + threadIdx.x) * 8;
    if (i >= n) return;
    float4 a = *(const float4*)(in + i);
    float4 b = *(const float4*)(in + i + 4);
    __half2 h0 = __floats2half2_rn(a.x, a.y);
    __half2 h1 = __floats2half2_rn(a.z, a.w);
    __half2 h2 = __floats2half2_rn(b.x, b.y);
    __half2 h3 = __floats2half2_rn(b.z, b.w);
    uint4 pk;
    pk.x = *(uint32_t*)&h0; pk.y = *(uint32_t*)&h1;
    pk.z = *(uint32_t*)&h2; pk.w = *(uint32_t*)&h3;
    *(uint4*)(out + i) = pk;
}

// ---------------------------------------------------------------------------
// fp16 GEMM (fp32 accum): C = A @ W^T + bias (+ Cadd)
// BM=256, BN=128, BK=64. 256 thr (8 warps), warp tile 64x64 (4x4 frags).
// 4-stage cp.async pipeline, 1 CTA/SM.
// ---------------------------------------------------------------------------
#define LDT 72                               // halfs per smem row (144 B)
#define STG_H ((256 + 128) * LDT)            // halfs per stage
#define STG_B (STG_H * 2)                    // 55296 B
#define GEMM_SMEM (STG_B * 4)                // 221184 B

template <bool ADDC>
__global__ void __launch_bounds__(256, 1)
gemm_h(const __half* __restrict__ A, const __half* __restrict__ W,
       const float* __restrict__ bias, const float* __restrict__ Cadd,
       float* __restrict__ C, int M, int N, int K)
{
    constexpr int LDO = 132;
    extern __shared__ __half sh[];
    float* sf = (float*)sh;

    const int t   = threadIdx.x;
    const int wid = t >> 5;
    const int bm  = blockIdx.y * 256;
    const int bn  = blockIdx.x * 128;
    const int wr  = wid & 3;     // 4 warp-rows of 64
    const int wc  = wid >> 2;    // 2 warp-cols of 64

    wmma::fragment<wmma::accumulator, 16, 16, 16, float> acc[4][4];
    #pragma unroll
    for (int i = 0; i < 4; i++)
        #pragma unroll
        for (int j = 0; j < 4; j++) wmma::fill_fragment(acc[i][j], 0.0f);

    const uint32_t sbase = (uint32_t)__cvta_generic_to_shared(sh);

    auto load_tile = [&](int s, int k0) {
        const uint32_t abase = sbase + s * STG_B;
        #pragma unroll
        for (int i = 0; i < 8; i++) {
            const int id = i * 256 + t;
            const int row = id >> 3, c = id & 7;
            cp16(abase + row * 144 + c * 16, A + (size_t)(bm + row) * K + k0 + c * 8);
        }
        const uint32_t bbase = abase + 256 * 144;
        #pragma unroll
        for (int i = 0; i < 4; i++) {
            const int id = i * 256 + t;
            const int row = id >> 3, c = id & 7;
            cp16(bbase + row * 144 + c * 16, W + (size_t)(bn + row) * K + k0 + c * 8);
        }
    };

    const int NK = K / 64;   // 8
    load_tile(0, 0);   asm volatile("cp.async.commit_group;");
    load_tile(1, 64);  asm volatile("cp.async.commit_group;");
    load_tile(2, 128); asm volatile("cp.async.commit_group;");

    for (int ks = 0; ks < NK; ks++) {
        asm volatile("cp.async.wait_group 2;");
        __syncthreads();

        const __half* a = sh + (ks & 3) * STG_H;
        const __half* w = a + 256 * LDT;
        #pragma unroll
        for (int kk = 0; kk < 64; kk += 16) {
            wmma::fragment<wmma::matrix_a, 16, 16, 16, __half, wmma::row_major> af[4];
            #pragma unroll
            for (int i = 0; i < 4; i++)
                wmma::load_matrix_sync(af[i], a + (wr * 64 + i * 16) * LDT + kk, LDT);
            #pragma unroll
            for (int j = 0; j < 4; j++) {
                wmma::fragment<wmma::matrix_b, 16, 16, 16, __half, wmma::col_major> bf;
                wmma::load_matrix_sync(bf, w + (wc * 64 + j * 16) * LDT + kk, LDT);
                #pragma unroll
                for (int i = 0; i < 4; i++)
                    wmma::mma_sync(acc[i][j], af[i], bf, acc[i][j]);
            }
        }
        if (ks + 3 < NK) load_tile((ks + 3) & 3, (ks + 3) * 64);
        asm volatile("cp.async.commit_group;");
    }
    __syncthreads();

    // Epilogue: frags -> smem(fp32, reuse pipeline smem) -> coalesced stores
    #pragma unroll
    for (int i = 0; i < 4; i++)
        #pragma unroll
        for (int j = 0; j < 4; j++)
            wmma::store_matrix_sync(sf + (wr * 64 + i * 16) * LDO + wc * 64 + j * 16,
                                    acc[i][j], LDO, wmma::mem_row_major);
    __syncthreads();

    #pragma unroll
    for (int rb = 0; rb < 2; rb++) {
        const int r  = rb * 128 + (t >> 1);
        const int cb = (t & 1) * 64;
        const size_t grow = (size_t)(bm + r) * N + bn;
        #pragma unroll
        for (int u = 0; u < 16; u++) {
            const int c = cb + u * 4;
            float4 v = *(float4*)&sf[r * LDO + c];
            v.x += bias[bn + c];     v.y += bias[bn + c + 1];
            v.z += bias[bn + c + 2]; v.w += bias[bn + c + 3];
            if (ADDC) {
                float4 d = *(const float4*)&Cadd[grow + c];
                v.x += d.x; v.y += d.y; v.z += d.z; v.w += d.w;
            }
            *(float4*)&C[grow + c] = v;
        }
    }
}

// ---------------------------------------------------------------------------
// Attention: one block per (b, h). 256 threads (8 warps). fp16 operands.
// ---------------------------------------------------------------------------
#define QKV_HALFS (3 * 128 * 72)
#define ATTN_SMEM_BYTES (QKV_HALFS * 2 + 128 * 132 * 4)

__global__ void attn_kernel(const float* __restrict__ qkv,
                            const float* __restrict__ corr,
                            const int*   __restrict__ mask,
                            const float* __restrict__ bscale,
                            __half* __restrict__ og)
{
    extern __shared__ __half smh[];
    __half* sQ = smh;                    // [128][72]
    __half* sK = sQ + 128 * 72;
    __half* sV = sK + 128 * 72;
    __half* sP = smh;                    // overlay Q..K after softmax [128][136]
    float*  sS = (float*)(smh + QKV_HALFS);   // [128][132]
    __shared__ __align__(16) float sB[128];

    const int bh = blockIdx.x;
    const int b  = bh >> 3;
    const int h  = bh & 7;
    const int t  = threadIdx.x;
    const int wid  = t >> 5;
    const int lane = t & 31;

    {
        const int row  = t >> 1;
        const int half = (t & 1) * 32;
        const size_t base = (size_t)(b * Lsz + row) * (3 * Dsz) + h * HDsz + half;
        const float* qp = qkv + base;
        const float* kp = qkv + base + Dsz;
        const float* vp = qkv + base + 2 * Dsz;
        __half* dq = &sQ[row * 72 + half];
        __half* dk = &sK[row * 72 + half];
        __half* dv = &sV[row * 72 + half];
        #pragma unroll
        for (int u = 0; u < 8; u++) {
            float4 q4 = *(const float4*)(qp + u * 4);
            float4 k4 = *(const float4*)(kp + u * 4);
            float4 v4 = *(const float4*)(vp + u * 4);
            *(__half2*)(dq + u * 4)     = __floats2half2_rn(q4.x * 0.125f, q4.y * 0.125f);
            *(__half2*)(dq + u * 4 + 2) = __floats2half2_rn(q4.z * 0.125f, q4.w * 0.125f);
            *(__half2*)(dk + u * 4)     = __floats2half2_rn(k4.x, k4.y);
            *(__half2*)(dk + u * 4 + 2) = __floats2half2_rn(k4.z, k4.w);
            *(__half2*)(dv + u * 4)     = __floats2half2_rn(v4.x, v4.y);
            *(__half2*)(dv + u * 4 + 2) = __floats2half2_rn(v4.z, v4.w);
        }
        if (t < 128) {
            const float bsc = bscale[0];
            sB[t] = mask[b * Lsz + t] ? -1e30f : bsc * corr[b * Lsz + t];
        }
    }
    __syncthreads();

    {
        const int wr = wid & 3, wc = wid >> 2;
        const int r0 = wr * 32, c0 = wc * 64;
        wmma::fragment<wmma::accumulator, 16, 16, 16, float> acc[2][4];
        #pragma unroll
        for (int i = 0; i < 2; i++)
            #pragma unroll
            for (int j = 0; j < 4; j++) wmma::fill_fragment(acc[i][j], 0.0f);

        #pragma unroll
        for (int kk = 0; kk < 64; kk += 16) {
            wmma::fragment<wmma::matrix_a, 16, 16, 16, __half, wmma::row_major> af[2];
            wmma::load_matrix_sync(af[0], &sQ[(r0 +  0) * 72 + kk], 72);
            wmma::load_matrix_sync(af[1], &sQ[(r0 + 16) * 72 + kk], 72);
            #pragma unroll
            for (int j = 0; j < 4; j++) {
                wmma::fragment<wmma::matrix_b, 16, 16, 16, __half, wmma::col_major> bf;
                wmma::load_matrix_sync(bf, &sK[(c0 + j * 16) * 72 + kk], 72);
                wmma::mma_sync(acc[0][j], af[0], bf, acc[0][j]);
                wmma::mma_sync(acc[1][j], af[1], bf, acc[1][j]);
            }
        }
        #pragma unroll
        for (int i = 0; i < 2; i++)
            #pragma unroll
            for (int j = 0; j < 4; j++)
                wmma::store_matrix_sync(&sS[(r0 + i * 16) * 132 + c0 + j * 16],
                                        acc[i][j], 132, wmma::mem_row_major);
    }
    __syncthreads();

    {
        const float4 bv = *(const float4*)&sB[lane * 4];
        #pragma unroll
        for (int rr = 0; rr < 16; rr++) {
            const int r = wid * 16 + rr;
            float4 v = *(float4*)&sS[r * 132 + lane * 4];
            v.x += bv.x; v.y += bv.y; v.z += bv.z; v.w += bv.w;
            float m = fmaxf(fmaxf(v.x, v.y), fmaxf(v.z, v.w));
            #pragma unroll
            for (int o = 16; o > 0; o >>= 1)
                m = fmaxf(m, __shfl_xor_sync(0xffffffffu, m, o));
            float4 e;
            e.x = __expf(v.x - m); e.y = __expf(v.y - m);
            e.z = __expf(v.z - m); e.w = __expf(v.w - m);
            float s = e.x + e.y + e.z + e.w;
            #pragma unroll
            for (int o = 16; o > 0; o >>= 1)
                s += __shfl_xor_sync(0xffffffffu, s, o);
            const float inv = 1.0f / s;
            *(__half2*)&sP[r * 136 + lane * 4]     = __floats2half2_rn(e.x * inv, e.y * inv);
            *(__half2*)&sP[r * 136 + lane * 4 + 2] = __floats2half2_rn(e.z * inv, e.w * inv);
        }
    }
    __syncthreads();

    {
        const int r0 = wid * 16;
        wmma::fragment<wmma::accumulator, 16, 16, 16, float> acc[4];
        #pragma unroll
        for (int c = 0; c < 4; c++) wmma::fill_fragment(acc[c], 0.0f);

        #pragma unroll
        for (int j = 0; j < 128; j += 16) {
            wmma::fragment<wmma::matrix_a, 16, 16, 16, __half, wmma::row_major> af;
            wmma::load_matrix_sync(af, &sP[r0 * 136 + j], 136);
            #pragma unroll
            for (int c = 0; c < 4; c++) {
                wmma::fragment<wmma::matrix_b, 16, 16, 16, __half, wmma::row_major> bf;
                wmma::load_matrix_sync(bf, &sV[j * 72 + c * 16], 72);
                wmma::mma_sync(acc[c], af, bf, acc[c]);
            }
        }
        #pragma unroll
        for (int c = 0; c < 4; c++)
            wmma::store_matrix_sync(&sS[r0 * 132 + c * 16], acc[c], 132, wmma::mem_row_major);
    }
    __syncthreads();

    {
        const int row  = t >> 1;
        const int half = (t & 1) * 32;
        __half* dst = og + (size_t)(b * Lsz + row) * Dsz + h * HDsz + half;
        const float* src = &sS[row * 132 + half];
        #pragma unroll
        for (int u = 0; u < 8; u++) {
            float4 v = *(const float4*)(src + u * 4);
            *(__half2*)(dst + u * 4)     = __floats2half2_rn(v.x, v.y);
            *(__half2*)(dst + u * 4 + 2) = __floats2half2_rn(v.z, v.w);
        }
    }
}

// ---------------------------------------------------------------------------
// LayerNorm: one block (128 threads) per row of 512.
// ---------------------------------------------------------------------------
__global__ void ln_kernel(const float* __restrict__ hbuf,
                          const float* __restrict__ lw,
                          const float* __restrict__ lb,
                          float* __restrict__ out)
{
    __shared__ float red[8];
    const int row  = blockIdx.x;
    const int t    = threadIdx.x;
    const int lane = t & 31;
    const int wid  = t >> 5;

    const size_t off = (size_t)row * Dsz + t * 4;
    float4 v = *(const float4*)&hbuf[off];
    float s  = v.x + v.y + v.z + v.w;
    float s2 = v.x*v.x + v.y*v.y + v.z*v.z + v.w*v.w;

    #pragma unroll
    for (int o = 16; o > 0; o >>= 1) {
        s  += __shfl_down_sync(0xffffffffu, s,  o);
        s2 += __shfl_down_sync(0xffffffffu, s2, o);
    }
    if (lane == 0) { red[wid] = s; red[4 + wid] = s2; }
    __syncthreads();
    s  = red[0] + red[1] + red[2] + red[3];
    s2 = red[4] + red[5] + red[6] + red[7];

    const float mu  = s * (1.0f / Dsz);
    const float var = s2 * (1.0f / Dsz) - mu * mu;
    const float inv = rsqrtf(var + LN_EPS);

    float4 w4 = *(const float4*)&lw[t * 4];
    float4 b4 = *(const float4*)&lb[t * 4];
    float4 r;
    r.x = (v.x - mu) * inv * w4.x + b4.x;
    r.y = (v.y - mu) * inv * w4.y + b4.y;
    r.z = (v.z - mu) * inv * w4.z + b4.z;
    r.w = (v.w - mu) * inv * w4.w + b4.w;
    *(float4*)&out[off] = r;
}

// ---------------------------------------------------------------------------
extern "C" void kernel_launch(void* const* d_in, const int* in_sizes, int n_in,
                              void* d_out, int out_size)
{
    const float* x      = (const float*)d_in[0];
    const float* corr   = (const float*)d_in[1];
    const int*   mask   = (const int*)  d_in[2];
    const float* in_w   = (const float*)d_in[3];
    const float* in_b   = (const float*)d_in[4];
    const float* out_w  = (const float*)d_in[5];
    const float* out_b  = (const float*)d_in[6];
    const float* ln_w   = (const float*)d_in[7];
    const float* ln_b   = (const float*)d_in[8];
    const float* bscale = (const float*)d_in[9];
    float* out = (float*)d_out;

    float *qkv, *h;
    __half *oh, *xh, *wih, *woh;
    cudaGetSymbolAddress((void**)&qkv, g_qkv);
    cudaGetSymbolAddress((void**)&oh,  g_oh);
    cudaGetSymbolAddress((void**)&h,   g_h);
    cudaGetSymbolAddress((void**)&xh,  g_xh);
    cudaGetSymbolAddress((void**)&wih, g_wih);
    cudaGetSymbolAddress((void**)&woh, g_woh);

    const int M = Bsz * Lsz;   // 65536

    cudaFuncSetAttribute(gemm_h<false>, cudaFuncAttributeMaxDynamicSharedMemorySize, GEMM_SMEM);
    cudaFuncSetAttribute(gemm_h<true>,  cudaFuncAttributeMaxDynamicSharedMemorySize, GEMM_SMEM);
    cudaFuncSetAttribute(attn_kernel, cudaFuncAttributeMaxDynamicSharedMemorySize, ATTN_SMEM_BYTES);

    // 0) fp32 -> fp16 conversions
    f2h_kernel<<<(M * Dsz / 8 + 255) / 256, 256>>>(x, xh, M * Dsz);
    f2h_kernel<<<(3 * Dsz * Dsz / 8 + 255) / 256, 256>>>(in_w, wih, 3 * Dsz * Dsz);
    f2h_kernel<<<(Dsz * Dsz / 8 + 255) / 256, 256>>>(out_w, woh, Dsz * Dsz);

    // 1) QKV projection
    gemm_h<false><<<dim3(3 * Dsz / 128, M / 256), 256, GEMM_SMEM>>>(
        xh, wih, in_b, nullptr, qkv, M, 3 * Dsz, Dsz);

    // 2) Attention per (b, h)
    attn_kernel<<<Bsz * Hn, 256, ATTN_SMEM_BYTES>>>(qkv, corr, mask, bscale, oh);

    // 3) out_proj + bias + residual
    gemm_h<true><<<dim3(Dsz / 128, M / 256), 256, GEMM_SMEM>>>(
        oh, woh, out_b, x, h, M, Dsz, Dsz);

    // 4) LayerNorm
    ln_kernel<<<M, 128>>>(h, ln_w, ln_b, out);
}

// round 7
// speedup vs baseline: 3.6279x; 1.3439x over previous
#include <cuda_runtime.h>
#include <mma.h>
#include <math.h>
#include <cstdint>
#include <cuda_fp16.h>

using namespace nvcuda;

#define Bsz 512
#define Lsz 128
#define Dsz 512
#define Hn  8
#define HDsz 64
#define LN_EPS 1e-5f

// Scratch (static device globals -- allocation-guard safe)
__device__ __half g_qkv[Bsz * Lsz * 3 * Dsz];    // (B, L, 1536) fp16
__device__ __half g_oh[Bsz * Lsz * Dsz];         // attention out, fp16
__device__ float  g_h[Bsz * Lsz * Dsz];          // residual+proj, fp32
__device__ __half g_xh[Bsz * Lsz * Dsz];         // x in fp16
__device__ __half g_wih[3 * Dsz * Dsz];          // in_proj_w fp16
__device__ __half g_woh[Dsz * Dsz];              // out_proj_w fp16

__device__ __forceinline__ void cp16(uint32_t d, const void* s) {
    asm volatile("cp.async.cg.shared.global [%0], [%1], 16;" :: "r"(d), "l"(s));
}

// ---------------------------------------------------------------------------
// fp32 -> fp16 conversion, 8 elems/thread
// ---------------------------------------------------------------------------
__global__ void f2h_kernel(const float* __restrict__ in, __half* __restrict__ out, int n)
{
    int i = (blockIdx.x * blockDim.x + threadIdx.x) * 8;
    if (i >= n) return;
    float4 a = *(const float4*)(in + i);
    float4 b = *(const float4*)(in + i + 4);
    __half2 h0 = __floats2half2_rn(a.x, a.y);
    __half2 h1 = __floats2half2_rn(a.z, a.w);
    __half2 h2 = __floats2half2_rn(b.x, b.y);
    __half2 h3 = __floats2half2_rn(b.z, b.w);
    uint4 pk;
    pk.x = *(uint32_t*)&h0; pk.y = *(uint32_t*)&h1;
    pk.z = *(uint32_t*)&h2; pk.w = *(uint32_t*)&h3;
    *(uint4*)(out + i) = pk;
}

// ---------------------------------------------------------------------------
// fp16 GEMM (fp32 accum): C = A @ W^T + bias (+ Cadd)
// BM=BN=128, BK=64. 256 thr (8 warps), warp tile 32x64. 3-stage cp.async.
// 2 CTAs/SM (regs capped at 128 by launch bounds, smem 110.6KB).
// ---------------------------------------------------------------------------
#define LDTh 72                               // halfs per smem row (144 B)
#define STG_HALFS (256 * LDTh)                // A(128)+B(128) rows per stage
#define STG_BYTES (STG_HALFS * 2)             // 36864 B
#define GEMM_SMEM (STG_BYTES * 3)             // 110592 B

template <bool ADDC, typename OutT>
__global__ void __launch_bounds__(256, 2)
gemm_h(const __half* __restrict__ A, const __half* __restrict__ W,
       const float* __restrict__ bias, const float* __restrict__ Cadd,
       OutT* __restrict__ C, int M, int N, int K)
{
    constexpr int LDO = 132;
    extern __shared__ __half sh[];
    float* sf = (float*)sh;

    const int t   = threadIdx.x;
    const int wid = t >> 5;
    const int bm  = blockIdx.y * 128;
    const int bn  = blockIdx.x * 128;
    const int wr  = wid & 3;     // 4 warp-rows of 32
    const int wc  = wid >> 2;    // 2 warp-cols of 64

    wmma::fragment<wmma::accumulator, 16, 16, 16, float> acc[2][4];
    #pragma unroll
    for (int i = 0; i < 2; i++)
        #pragma unroll
        for (int j = 0; j < 4; j++) wmma::fill_fragment(acc[i][j], 0.0f);

    const uint32_t sbase = (uint32_t)__cvta_generic_to_shared(sh);

    auto load_tile = [&](int s, int k0) {
        const uint32_t base = sbase + s * STG_BYTES;
        #pragma unroll
        for (int i = 0; i < 4; i++) {           // A: 128 rows x 8 chunks
            const int j = i * 256 + t;
            const int row = j >> 3, c = j & 7;
            cp16(base + row * 144 + c * 16, A + (size_t)(bm + row) * K + k0 + c * 8);
        }
        const uint32_t bb = base + 128 * 144;
        #pragma unroll
        for (int i = 0; i < 4; i++) {           // B: 128 rows x 8 chunks
            const int j = i * 256 + t;
            const int row = j >> 3, c = j & 7;
            cp16(bb + row * 144 + c * 16, W + (size_t)(bn + row) * K + k0 + c * 8);
        }
    };

    const int NK = K / 64;   // 8
    load_tile(0, 0);  asm volatile("cp.async.commit_group;");
    load_tile(1, 64); asm volatile("cp.async.commit_group;");

    for (int ks = 0; ks < NK; ks++) {
        asm volatile("cp.async.wait_group 1;");
        __syncthreads();

        const __half* a = sh + (ks % 3) * STG_HALFS;
        const __half* w = a + 128 * LDTh;
        #pragma unroll
        for (int kk = 0; kk < 64; kk += 16) {
            wmma::fragment<wmma::matrix_a, 16, 16, 16, __half, wmma::row_major> af[2];
            wmma::load_matrix_sync(af[0], a + (wr * 32) * LDTh + kk, LDTh);
            wmma::load_matrix_sync(af[1], a + (wr * 32 + 16) * LDTh + kk, LDTh);
            #pragma unroll
            for (int j = 0; j < 4; j++) {
                wmma::fragment<wmma::matrix_b, 16, 16, 16, __half, wmma::col_major> bf;
                wmma::load_matrix_sync(bf, w + (wc * 64 + j * 16) * LDTh + kk, LDTh);
                wmma::mma_sync(acc[0][j], af[0], bf, acc[0][j]);
                wmma::mma_sync(acc[1][j], af[1], bf, acc[1][j]);
            }
        }
        if (ks + 2 < NK) load_tile((ks + 2) % 3, (ks + 2) * 64);
        asm volatile("cp.async.commit_group;");
    }
    __syncthreads();

    // Epilogue: frags -> smem(fp32) -> coalesced stores
    #pragma unroll
    for (int i = 0; i < 2; i++)
        #pragma unroll
        for (int j = 0; j < 4; j++)
            wmma::store_matrix_sync(sf + (wr * 32 + i * 16) * LDO + wc * 64 + j * 16,
                                    acc[i][j], LDO, wmma::mem_row_major);
    __syncthreads();

    const int r  = t >> 1;
    const int cb = (t & 1) * 64;
    const size_t grow = (size_t)(bm + r) * N + bn;
    #pragma unroll
    for (int u = 0; u < 16; u++) {
        const int c = cb + u * 4;
        float4 v = *(float4*)&sf[r * LDO + c];
        v.x += bias[bn + c];     v.y += bias[bn + c + 1];
        v.z += bias[bn + c + 2]; v.w += bias[bn + c + 3];
        if (ADDC) {
            float4 d = *(const float4*)&Cadd[grow + c];
            v.x += d.x; v.y += d.y; v.z += d.z; v.w += d.w;
        }
        if (sizeof(OutT) == 2) {
            __half2 h0 = __floats2half2_rn(v.x, v.y);
            __half2 h1 = __floats2half2_rn(v.z, v.w);
            uint2 pk; pk.x = *(uint32_t*)&h0; pk.y = *(uint32_t*)&h1;
            *(uint2*)((__half*)C + grow + c) = pk;
        } else {
            *(float4*)((float*)C + grow + c) = v;
        }
    }
}

// ---------------------------------------------------------------------------
// Attention: one block per (b, h). 256 threads (8 warps). 2 CTAs/SM.
// smem: Q[128][72]h, K[128][72]h (V overlays K), S fp32 [128][132]
// (P fp16 overlays S rows in place, stride 264 halfs).
// ---------------------------------------------------------------------------
#define ATTN_DYN (2 * 128 * 72 * 2 + 128 * 132 * 4)   // 104448 B

__global__ void __launch_bounds__(256, 2)
attn_kernel(const __half* __restrict__ qkv,
            const float* __restrict__ corr,
            const int*   __restrict__ mask,
            const float* __restrict__ bscale,
            __half* __restrict__ og)
{
    extern __shared__ __half smh[];
    __half* sQ = smh;                        // [128][72]
    __half* sK = smh + 128 * 72;             // [128][72]; V overlays after S
    float*  sS = (float*)(smh + 2 * 128 * 72);   // [128][132]; P overlays rows
    __half* sP = (__half*)sS;                // P row stride 264 halfs
    __half* sV = sK;
    __shared__ __align__(16) float sB[128];

    const int bh = blockIdx.x;
    const int b  = bh >> 3;
    const int h  = bh & 7;
    const int t  = threadIdx.x;
    const int wid  = t >> 5;

    const uint32_t qb = (uint32_t)__cvta_generic_to_shared(sQ);
    const uint32_t kb = (uint32_t)__cvta_generic_to_shared(sK);
    const __half* src = qkv + (size_t)(b * Lsz) * (3 * Dsz) + h * HDsz;

    // ---- cp.async Q, K (fp16, 128B rows) ----
    #pragma unroll
    for (int i = 0; i < 4; i++) {
        const int j = i * 256 + t;
        const int row = j >> 3, c = j & 7;
        cp16(qb + row * 144 + c * 16, src + (size_t)row * 1536 + c * 8);
        cp16(kb + row * 144 + c * 16, src + (size_t)row * 1536 + 512 + c * 8);
    }
    asm volatile("cp.async.commit_group;");
    if (t < 128) {
        const float bsc = bscale[0];
        sB[t] = mask[b * Lsz + t] ? -1e30f : bsc * corr[b * Lsz + t];
    }
    asm volatile("cp.async.wait_group 0;");
    __syncthreads();

    // ---- S = Q @ K^T : warp grid 4x2, each warp 32x64 ----
    {
        const int wr = wid & 3, wc = wid >> 2;
        const int r0 = wr * 32, c0 = wc * 64;
        wmma::fragment<wmma::accumulator, 16, 16, 16, float> acc[2][4];
        #pragma unroll
        for (int i = 0; i < 2; i++)
            #pragma unroll
            for (int j = 0; j < 4; j++) wmma::fill_fragment(acc[i][j], 0.0f);

        #pragma unroll
        for (int kk = 0; kk < 64; kk += 16) {
            wmma::fragment<wmma::matrix_a, 16, 16, 16, __half, wmma::row_major> af[2];
            wmma::load_matrix_sync(af[0], &sQ[(r0 +  0) * 72 + kk], 72);
            wmma::load_matrix_sync(af[1], &sQ[(r0 + 16) * 72 + kk], 72);
            #pragma unroll
            for (int j = 0; j < 4; j++) {
                wmma::fragment<wmma::matrix_b, 16, 16, 16, __half, wmma::col_major> bf;
                wmma::load_matrix_sync(bf, &sK[(c0 + j * 16) * 72 + kk], 72);
                wmma::mma_sync(acc[0][j], af[0], bf, acc[0][j]);
                wmma::mma_sync(acc[1][j], af[1], bf, acc[1][j]);
            }
        }
        #pragma unroll
        for (int i = 0; i < 2; i++)
            #pragma unroll
            for (int j = 0; j < 4; j++)
                wmma::store_matrix_sync(&sS[(r0 + i * 16) * 132 + c0 + j * 16],
                                        acc[i][j], 132, wmma::mem_row_major);
    }
    __syncthreads();

    // ---- issue V cp.async into K region (K is dead); overlaps softmax ----
    #pragma unroll
    for (int i = 0; i < 4; i++) {
        const int j = i * 256 + t;
        const int row = j >> 3, c = j & 7;
        cp16(kb + row * 144 + c * 16, src + (size_t)row * 1536 + 1024 + c * 8);
    }
    asm volatile("cp.async.commit_group;");

    // ---- softmax: 2 threads per row, 64 cols each; P fp16 in place over S ----
    {
        const int r   = t >> 1;
        const int seg = t & 1;
        const float* srow = &sS[r * 132 + seg * 64];
        const float* brow = &sB[seg * 64];
        float v[64];
        float m = -1e30f;
        #pragma unroll
        for (int u = 0; u < 16; u++) {
            float4 s4 = *(const float4*)(srow + u * 4);
            float4 b4 = *(const float4*)(brow + u * 4);
            v[u*4+0] = fmaf(s4.x, 0.125f, b4.x);
            v[u*4+1] = fmaf(s4.y, 0.125f, b4.y);
            v[u*4+2] = fmaf(s4.z, 0.125f, b4.z);
            v[u*4+3] = fmaf(s4.w, 0.125f, b4.w);
            m = fmaxf(m, fmaxf(fmaxf(v[u*4], v[u*4+1]), fmaxf(v[u*4+2], v[u*4+3])));
        }
        m = fmaxf(m, __shfl_xor_sync(0xffffffffu, m, 1));
        float s = 0.0f;
        #pragma unroll
        for (int u = 0; u < 64; u++) { v[u] = __expf(v[u] - m); s += v[u]; }
        s += __shfl_xor_sync(0xffffffffu, s, 1);
        const float inv = 1.0f / s;
        __half* prow = sP + r * 264 + seg * 64;
        #pragma unroll
        for (int u = 0; u < 8; u++) {
            __half2 p0 = __floats2half2_rn(v[u*8+0] * inv, v[u*8+1] * inv);
            __half2 p1 = __floats2half2_rn(v[u*8+2] * inv, v[u*8+3] * inv);
            __half2 p2 = __floats2half2_rn(v[u*8+4] * inv, v[u*8+5] * inv);
            __half2 p3 = __floats2half2_rn(v[u*8+6] * inv, v[u*8+7] * inv);
            uint4 pk;
            pk.x = *(uint32_t*)&p0; pk.y = *(uint32_t*)&p1;
            pk.z = *(uint32_t*)&p2; pk.w = *(uint32_t*)&p3;
            *(uint4*)(prow + u * 8) = pk;
        }
    }
    asm volatile("cp.async.wait_group 0;");
    __syncthreads();

    // ---- O = P @ V : each warp 16 rows x 64 cols; O overwrites own P rows ----
    {
        const int r0 = wid * 16;
        wmma::fragment<wmma::accumulator, 16, 16, 16, float> acc[4];
        #pragma unroll
        for (int c = 0; c < 4; c++) wmma::fill_fragment(acc[c], 0.0f);

        #pragma unroll
        for (int j = 0; j < 128; j += 16) {
            wmma::fragment<wmma::matrix_a, 16, 16, 16, __half, wmma::row_major> af;
            wmma::load_matrix_sync(af, &sP[r0 * 264 + j], 264);
            #pragma unroll
            for (int c = 0; c < 4; c++) {
                wmma::fragment<wmma::matrix_b, 16, 16, 16, __half, wmma::row_major> bf;
                wmma::load_matrix_sync(bf, &sV[j * 72 + c * 16], 72);
                wmma::mma_sync(acc[c], af, bf, acc[c]);
            }
        }
        #pragma unroll
        for (int c = 0; c < 4; c++)
            wmma::store_matrix_sync(&sS[r0 * 132 + c * 16], acc[c], 132, wmma::mem_row_major);
    }
    __syncthreads();

    // ---- convert O to fp16, coalesced store ----
    {
        const int r   = t >> 1;
        const int seg = (t & 1) * 32;
        __half* dst = og + (size_t)(b * Lsz + r) * Dsz + h * HDsz + seg;
        const float* srcO = &sS[r * 132 + seg];
        #pragma unroll
        for (int u = 0; u < 4; u++) {
            float4 a = *(const float4*)(srcO + u * 8);
            float4 c = *(const float4*)(srcO + u * 8 + 4);
            __half2 h0 = __floats2half2_rn(a.x, a.y);
            __half2 h1 = __floats2half2_rn(a.z, a.w);
            __half2 h2 = __floats2half2_rn(c.x, c.y);
            __half2 h3 = __floats2half2_rn(c.z, c.w);
            uint4 pk;
            pk.x = *(uint32_t*)&h0; pk.y = *(uint32_t*)&h1;
            pk.z = *(uint32_t*)&h2; pk.w = *(uint32_t*)&h3;
            *(uint4*)(dst + u * 8) = pk;
        }
    }
}

// ---------------------------------------------------------------------------
// LayerNorm: one block (128 threads) per row of 512.
// ---------------------------------------------------------------------------
__global__ void ln_kernel(const float* __restrict__ hbuf,
                          const float* __restrict__ lw,
                          const float* __restrict__ lb,
                          float* __restrict__ out)
{
    __shared__ float red[8];
    const int row  = blockIdx.x;
    const int t    = threadIdx.x;
    const int lane = t & 31;
    const int wid  = t >> 5;

    const size_t off = (size_t)row * Dsz + t * 4;
    float4 v = *(const float4*)&hbuf[off];
    float s  = v.x + v.y + v.z + v.w;
    float s2 = v.x*v.x + v.y*v.y + v.z*v.z + v.w*v.w;

    #pragma unroll
    for (int o = 16; o > 0; o >>= 1) {
        s  += __shfl_down_sync(0xffffffffu, s,  o);
        s2 += __shfl_down_sync(0xffffffffu, s2, o);
    }
    if (lane == 0) { red[wid] = s; red[4 + wid] = s2; }
    __syncthreads();
    s  = red[0] + red[1] + red[2] + red[3];
    s2 = red[4] + red[5] + red[6] + red[7];

    const float mu  = s * (1.0f / Dsz);
    const float var = s2 * (1.0f / Dsz) - mu * mu;
    const float inv = rsqrtf(var + LN_EPS);

    float4 w4 = *(const float4*)&lw[t * 4];
    float4 b4 = *(const float4*)&lb[t * 4];
    float4 r;
    r.x = (v.x - mu) * inv * w4.x + b4.x;
    r.y = (v.y - mu) * inv * w4.y + b4.y;
    r.z = (v.z - mu) * inv * w4.z + b4.z;
    r.w = (v.w - mu) * inv * w4.w + b4.w;
    *(float4*)&out[off] = r;
}

// ---------------------------------------------------------------------------
extern "C" void kernel_launch(void* const* d_in, const int* in_sizes, int n_in,
                              void* d_out, int out_size)
{
    const float* x      = (const float*)d_in[0];
    const float* corr   = (const float*)d_in[1];
    const int*   mask   = (const int*)  d_in[2];
    const float* in_w   = (const float*)d_in[3];
    const float* in_b   = (const float*)d_in[4];
    const float* out_w  = (const float*)d_in[5];
    const float* out_b  = (const float*)d_in[6];
    const float* ln_w   = (const float*)d_in[7];
    const float* ln_b   = (const float*)d_in[8];
    const float* bscale = (const float*)d_in[9];
    float* out = (float*)d_out;

    float *h;
    __half *qkv, *oh, *xh, *wih, *woh;
    cudaGetSymbolAddress((void**)&qkv, g_qkv);
    cudaGetSymbolAddress((void**)&oh,  g_oh);
    cudaGetSymbolAddress((void**)&h,   g_h);
    cudaGetSymbolAddress((void**)&xh,  g_xh);
    cudaGetSymbolAddress((void**)&wih, g_wih);
    cudaGetSymbolAddress((void**)&woh, g_woh);

    const int M = Bsz * Lsz;   // 65536

    cudaFuncSetAttribute((void*)gemm_h<false, __half>, cudaFuncAttributeMaxDynamicSharedMemorySize, GEMM_SMEM);
    cudaFuncSetAttribute((void*)gemm_h<true, float>,   cudaFuncAttributeMaxDynamicSharedMemorySize, GEMM_SMEM);
    cudaFuncSetAttribute((void*)attn_kernel, cudaFuncAttributeMaxDynamicSharedMemorySize, ATTN_DYN);

    // 0) fp32 -> fp16 conversions
    f2h_kernel<<<(M * Dsz / 8 + 255) / 256, 256>>>(x, xh, M * Dsz);
    f2h_kernel<<<(3 * Dsz * Dsz / 8 + 255) / 256, 256>>>(in_w, wih, 3 * Dsz * Dsz);
    f2h_kernel<<<(Dsz * Dsz / 8 + 255) / 256, 256>>>(out_w, woh, Dsz * Dsz);

    // 1) QKV projection -> fp16 qkv
    gemm_h<false, __half><<<dim3(3 * Dsz / 128, M / 128), 256, GEMM_SMEM>>>(
        xh, wih, in_b, nullptr, qkv, M, 3 * Dsz, Dsz);

    // 2) Attention per (b, h)
    attn_kernel<<<Bsz * Hn, 256, ATTN_DYN>>>(qkv, corr, mask, bscale, oh);

    // 3) out_proj + bias + residual -> fp32 h
    gemm_h<true, float><<<dim3(Dsz / 128, M / 128), 256, GEMM_SMEM>>>(
        oh, woh, out_b, x, h, M, Dsz, Dsz);

    // 4) LayerNorm
    ln_kernel<<<M, 128>>>(h, ln_w, ln_b, out);
}

// round 8
// speedup vs baseline: 3.8760x; 1.0684x over previous
#include <cuda_runtime.h>
#include <mma.h>
#include <math.h>
#include <cstdint>
#include <cuda_fp16.h>

using namespace nvcuda;

#define Bsz 512
#define Lsz 128
#define Dsz 512
#define Hn  8
#define HDsz 64
#define LN_EPS 1e-5f

// Scratch (static device globals -- allocation-guard safe)
__device__ __half g_qkv[Bsz * Lsz * 3 * Dsz];    // (B, L, 1536) fp16
__device__ __half g_oh[Bsz * Lsz * Dsz];         // attention out, fp16
__device__ __half g_xh[Bsz * Lsz * Dsz];         // x in fp16
__device__ __half g_wih[3 * Dsz * Dsz];          // in_proj_w fp16
__device__ __half g_woh[Dsz * Dsz];              // out_proj_w fp16

__device__ __forceinline__ void cp16(uint32_t d, const void* s) {
    asm volatile("cp.async.cg.shared.global [%0], [%1], 16;" :: "r"(d), "l"(s));
}

// ---------------------------------------------------------------------------
// fp32 -> fp16 conversion for x, in_w, out_w in ONE launch.
// Each block converts 2048 elems. Regions: x 16384 blocks, in_w 384, out_w 128.
// ---------------------------------------------------------------------------
__global__ void f2h_multi(const float* __restrict__ x,   __half* __restrict__ xh,
                          const float* __restrict__ w1,  __half* __restrict__ w1h,
                          const float* __restrict__ w2,  __half* __restrict__ w2h)
{
    const int bid = blockIdx.x;
    const float* in; __half* out; int base;
    if (bid < 16384)      { in = x;  out = xh;  base = bid; }
    else if (bid < 16768) { in = w1; out = w1h; base = bid - 16384; }
    else                  { in = w2; out = w2h; base = bid - 16768; }
    const int i = base * 2048 + threadIdx.x * 8;
    float4 a = *(const float4*)(in + i);
    float4 b = *(const float4*)(in + i + 4);
    __half2 h0 = __floats2half2_rn(a.x, a.y);
    __half2 h1 = __floats2half2_rn(a.z, a.w);
    __half2 h2 = __floats2half2_rn(b.x, b.y);
    __half2 h3 = __floats2half2_rn(b.z, b.w);
    uint4 pk;
    pk.x = *(uint32_t*)&h0; pk.y = *(uint32_t*)&h1;
    pk.z = *(uint32_t*)&h2; pk.w = *(uint32_t*)&h3;
    *(uint4*)(out + i) = pk;
}

// ---------------------------------------------------------------------------
// fp16 GEMM (fp32 accum): C = A @ W^T + bias.  (QKV projection)
// BM=BN=128, BK=64. 256 thr (8 warps), warp tile 32x64. 3-stage cp.async.
// ---------------------------------------------------------------------------
#define LDTh 72
#define STG_HALFS (256 * LDTh)
#define STG_BYTES (STG_HALFS * 2)             // 36864 B
#define GEMM_SMEM (STG_BYTES * 3)             // 110592 B

__global__ void __launch_bounds__(256, 2)
gemm_qkv(const __half* __restrict__ A, const __half* __restrict__ W,
         const float* __restrict__ bias, __half* __restrict__ C, int M, int N, int K)
{
    constexpr int LDO = 132;
    extern __shared__ __half sh[];
    float* sf = (float*)sh;

    const int t   = threadIdx.x;
    const int wid = t >> 5;
    const int bm  = blockIdx.y * 128;
    const int bn  = blockIdx.x * 128;
    const int wr  = wid & 3;
    const int wc  = wid >> 2;

    wmma::fragment<wmma::accumulator, 16, 16, 16, float> acc[2][4];
    #pragma unroll
    for (int i = 0; i < 2; i++)
        #pragma unroll
        for (int j = 0; j < 4; j++) wmma::fill_fragment(acc[i][j], 0.0f);

    const uint32_t sbase = (uint32_t)__cvta_generic_to_shared(sh);

    auto load_tile = [&](int s, int k0) {
        const uint32_t base = sbase + s * STG_BYTES;
        #pragma unroll
        for (int i = 0; i < 4; i++) {
            const int j = i * 256 + t;
            const int row = j >> 3, c = j & 7;
            cp16(base + row * 144 + c * 16, A + (size_t)(bm + row) * K + k0 + c * 8);
        }
        const uint32_t bb = base + 128 * 144;
        #pragma unroll
        for (int i = 0; i < 4; i++) {
            const int j = i * 256 + t;
            const int row = j >> 3, c = j & 7;
            cp16(bb + row * 144 + c * 16, W + (size_t)(bn + row) * K + k0 + c * 8);
        }
    };

    const int NK = K / 64;   // 8
    load_tile(0, 0);  asm volatile("cp.async.commit_group;");
    load_tile(1, 64); asm volatile("cp.async.commit_group;");

    for (int ks = 0; ks < NK; ks++) {
        asm volatile("cp.async.wait_group 1;");
        __syncthreads();
        // issue next-stage loads BEFORE compute for max overlap
        if (ks + 2 < NK) load_tile((ks + 2) % 3, (ks + 2) * 64);
        asm volatile("cp.async.commit_group;");

        const __half* a = sh + (ks % 3) * STG_HALFS;
        const __half* w = a + 128 * LDTh;
        #pragma unroll
        for (int kk = 0; kk < 64; kk += 16) {
            wmma::fragment<wmma::matrix_a, 16, 16, 16, __half, wmma::row_major> af[2];
            wmma::load_matrix_sync(af[0], a + (wr * 32) * LDTh + kk, LDTh);
            wmma::load_matrix_sync(af[1], a + (wr * 32 + 16) * LDTh + kk, LDTh);
            #pragma unroll
            for (int j = 0; j < 4; j++) {
                wmma::fragment<wmma::matrix_b, 16, 16, 16, __half, wmma::col_major> bf;
                wmma::load_matrix_sync(bf, w + (wc * 64 + j * 16) * LDTh + kk, LDTh);
                wmma::mma_sync(acc[0][j], af[0], bf, acc[0][j]);
                wmma::mma_sync(acc[1][j], af[1], bf, acc[1][j]);
            }
        }
    }
    __syncthreads();

    #pragma unroll
    for (int i = 0; i < 2; i++)
        #pragma unroll
        for (int j = 0; j < 4; j++)
            wmma::store_matrix_sync(sf + (wr * 32 + i * 16) * LDO + wc * 64 + j * 16,
                                    acc[i][j], LDO, wmma::mem_row_major);
    __syncthreads();

    const int r  = t >> 1;
    const int cb = (t & 1) * 64;
    const size_t grow = (size_t)(bm + r) * N + bn;
    #pragma unroll
    for (int u = 0; u < 16; u++) {
        const int c = cb + u * 4;
        float4 v = *(float4*)&sf[r * LDO + c];
        v.x += bias[bn + c];     v.y += bias[bn + c + 1];
        v.z += bias[bn + c + 2]; v.w += bias[bn + c + 3];
        __half2 h0 = __floats2half2_rn(v.x, v.y);
        __half2 h1 = __floats2half2_rn(v.z, v.w);
        uint2 pk; pk.x = *(uint32_t*)&h0; pk.y = *(uint32_t*)&h1;
        *(uint2*)((__half*)C + grow + c) = pk;
    }
}

// ---------------------------------------------------------------------------
// Fused out_proj + bias + residual + LayerNorm.
// BM=64, BN=512 (full rows per CTA), BK=32, 512 thr (16 warps), 3-stage.
// grid = M/64 = 1024. Warp tile 32x64 (grid 2x8).
// ---------------------------------------------------------------------------
#define LDTb 40                                // halfs per row (80 B)
#define OP_B_BYTES (512 * 80)                  // 40960
#define OP_A_BYTES (64 * 80)                   // 5120
#define OP_STG (OP_B_BYTES + OP_A_BYTES)       // 46080
#define OPLN_SMEM (OP_STG * 3)                 // 138240
#define LDOo 516

__global__ void __launch_bounds__(512, 1)
outproj_ln(const __half* __restrict__ A, const __half* __restrict__ W,
           const float* __restrict__ out_b, const float* __restrict__ x,
           const float* __restrict__ lnw, const float* __restrict__ lnb,
           float* __restrict__ out)
{
    extern __shared__ __half sh[];
    float* sf = (float*)sh;

    const int t   = threadIdx.x;
    const int wid = t >> 5;
    const int bm  = blockIdx.x * 64;
    const int wr  = wid & 1;      // 2 warp-rows of 32
    const int wc  = wid >> 1;     // 8 warp-cols of 64

    wmma::fragment<wmma::accumulator, 16, 16, 16, float> acc[2][4];
    #pragma unroll
    for (int i = 0; i < 2; i++)
        #pragma unroll
        for (int j = 0; j < 4; j++) wmma::fill_fragment(acc[i][j], 0.0f);

    const uint32_t sbase = (uint32_t)__cvta_generic_to_shared(sh);

    auto load_tile = [&](int s, int k0) {
        const uint32_t base = sbase + s * OP_STG;
        #pragma unroll
        for (int i = 0; i < 4; i++) {      // B: 512 rows x 4 chunks of 16B
            const int j = i * 512 + t;
            const int row = j >> 2, c = j & 3;
            cp16(base + row * 80 + c * 16, W + (size_t)row * Dsz + k0 + c * 8);
        }
        if (t < 256) {                     // A: 64 rows x 4 chunks
            const int row = t >> 2, c = t & 3;
            cp16(base + OP_B_BYTES + row * 80 + c * 16,
                 A + (size_t)(bm + row) * Dsz + k0 + c * 8);
        }
    };

    const int NK = Dsz / 32;   // 16
    load_tile(0, 0);  asm volatile("cp.async.commit_group;");
    load_tile(1, 32); asm volatile("cp.async.commit_group;");

    for (int ks = 0; ks < NK; ks++) {
        asm volatile("cp.async.wait_group 1;");
        __syncthreads();
        if (ks + 2 < NK) load_tile((ks + 2) % 3, (ks + 2) * 32);
        asm volatile("cp.async.commit_group;");

        const __half* bsm = sh + (ks % 3) * (OP_STG / 2);
        const __half* asm_ = bsm + OP_B_BYTES / 2;
        #pragma unroll
        for (int kk = 0; kk < 32; kk += 16) {
            wmma::fragment<wmma::matrix_a, 16, 16, 16, __half, wmma::row_major> af[2];
            wmma::load_matrix_sync(af[0], asm_ + (wr * 32) * LDTb + kk, LDTb);
            wmma::load_matrix_sync(af[1], asm_ + (wr * 32 + 16) * LDTb + kk, LDTb);
            #pragma unroll
            for (int j = 0; j < 4; j++) {
                wmma::fragment<wmma::matrix_b, 16, 16, 16, __half, wmma::col_major> bf;
                wmma::load_matrix_sync(bf, bsm + (wc * 64 + j * 16) * LDTb + kk, LDTb);
                wmma::mma_sync(acc[0][j], af[0], bf, acc[0][j]);
                wmma::mma_sync(acc[1][j], af[1], bf, acc[1][j]);
            }
        }
    }
    __syncthreads();

    // acc -> smem fp32 [64][516]
    #pragma unroll
    for (int i = 0; i < 2; i++)
        #pragma unroll
        for (int j = 0; j < 4; j++)
            wmma::store_matrix_sync(sf + (wr * 32 + i * 16) * LDOo + wc * 64 + j * 16,
                                    acc[i][j], LDOo, wmma::mem_row_major);
    __syncthreads();

    // LayerNorm: 8 threads per row; thread covers cols (t&7)*4 + 32u (u=0..15)
    {
        const int row = t >> 3;
        const int l8  = t & 7;
        const int gr  = bm + row;
        float v[64];
        float s = 0.0f, s2 = 0.0f;
        #pragma unroll
        for (int u = 0; u < 16; u++) {
            const int c = l8 * 4 + u * 32;
            float4 a4 = *(float4*)&sf[row * LDOo + c];
            float4 b4 = *(const float4*)&out_b[c];
            float4 x4 = *(const float4*)&x[(size_t)gr * Dsz + c];
            a4.x += b4.x + x4.x; a4.y += b4.y + x4.y;
            a4.z += b4.z + x4.z; a4.w += b4.w + x4.w;
            v[u*4+0] = a4.x; v[u*4+1] = a4.y; v[u*4+2] = a4.z; v[u*4+3] = a4.w;
            s  += a4.x + a4.y + a4.z + a4.w;
            s2 += a4.x*a4.x + a4.y*a4.y + a4.z*a4.z + a4.w*a4.w;
        }
        #pragma unroll
        for (int o = 1; o < 8; o <<= 1) {
            s  += __shfl_xor_sync(0xffffffffu, s,  o);
            s2 += __shfl_xor_sync(0xffffffffu, s2, o);
        }
        const float mu  = s * (1.0f / Dsz);
        const float var = s2 * (1.0f / Dsz) - mu * mu;
        const float inv = rsqrtf(var + LN_EPS);
        #pragma unroll
        for (int u = 0; u < 16; u++) {
            const int c = l8 * 4 + u * 32;
            float4 w4 = *(const float4*)&lnw[c];
            float4 b4 = *(const float4*)&lnb[c];
            float4 r;
            r.x = (v[u*4+0] - mu) * inv * w4.x + b4.x;
            r.y = (v[u*4+1] - mu) * inv * w4.y + b4.y;
            r.z = (v[u*4+2] - mu) * inv * w4.z + b4.z;
            r.w = (v[u*4+3] - mu) * inv * w4.w + b4.w;
            *(float4*)&out[(size_t)gr * Dsz + c] = r;
        }
    }
}

// ---------------------------------------------------------------------------
// Attention: one block per (b, h). 256 threads (8 warps). 2 CTAs/SM.
// ---------------------------------------------------------------------------
#define ATTN_DYN (2 * 128 * 72 * 2 + 128 * 132 * 4)   // 104448 B

__global__ void __launch_bounds__(256, 2)
attn_kernel(const __half* __restrict__ qkv,
            const float* __restrict__ corr,
            const int*   __restrict__ mask,
            const float* __restrict__ bscale,
            __half* __restrict__ og)
{
    extern __shared__ __half smh[];
    __half* sQ = smh;
    __half* sK = smh + 128 * 72;
    float*  sS = (float*)(smh + 2 * 128 * 72);
    __half* sP = (__half*)sS;
    __half* sV = sK;
    __shared__ __align__(16) float sB[128];

    const int bh = blockIdx.x;
    const int b  = bh >> 3;
    const int h  = bh & 7;
    const int t  = threadIdx.x;
    const int wid  = t >> 5;

    const uint32_t qb = (uint32_t)__cvta_generic_to_shared(sQ);
    const uint32_t kb = (uint32_t)__cvta_generic_to_shared(sK);
    const __half* src = qkv + (size_t)(b * Lsz) * (3 * Dsz) + h * HDsz;

    #pragma unroll
    for (int i = 0; i < 4; i++) {
        const int j = i * 256 + t;
        const int row = j >> 3, c = j & 7;
        cp16(qb + row * 144 + c * 16, src + (size_t)row * 1536 + c * 8);
        cp16(kb + row * 144 + c * 16, src + (size_t)row * 1536 + 512 + c * 8);
    }
    asm volatile("cp.async.commit_group;");
    if (t < 128) {
        const float bsc = bscale[0];
        sB[t] = mask[b * Lsz + t] ? -1e30f : bsc * corr[b * Lsz + t];
    }
    asm volatile("cp.async.wait_group 0;");
    __syncthreads();

    {
        const int wr = wid & 3, wc = wid >> 2;
        const int r0 = wr * 32, c0 = wc * 64;
        wmma::fragment<wmma::accumulator, 16, 16, 16, float> acc[2][4];
        #pragma unroll
        for (int i = 0; i < 2; i++)
            #pragma unroll
            for (int j = 0; j < 4; j++) wmma::fill_fragment(acc[i][j], 0.0f);

        #pragma unroll
        for (int kk = 0; kk < 64; kk += 16) {
            wmma::fragment<wmma::matrix_a, 16, 16, 16, __half, wmma::row_major> af[2];
            wmma::load_matrix_sync(af[0], &sQ[(r0 +  0) * 72 + kk], 72);
            wmma::load_matrix_sync(af[1], &sQ[(r0 + 16) * 72 + kk], 72);
            #pragma unroll
            for (int j = 0; j < 4; j++) {
                wmma::fragment<wmma::matrix_b, 16, 16, 16, __half, wmma::col_major> bf;
                wmma::load_matrix_sync(bf, &sK[(c0 + j * 16) * 72 + kk], 72);
                wmma::mma_sync(acc[0][j], af[0], bf, acc[0][j]);
                wmma::mma_sync(acc[1][j], af[1], bf, acc[1][j]);
            }
        }
        #pragma unroll
        for (int i = 0; i < 2; i++)
            #pragma unroll
            for (int j = 0; j < 4; j++)
                wmma::store_matrix_sync(&sS[(r0 + i * 16) * 132 + c0 + j * 16],
                                        acc[i][j], 132, wmma::mem_row_major);
    }
    __syncthreads();

    #pragma unroll
    for (int i = 0; i < 4; i++) {
        const int j = i * 256 + t;
        const int row = j >> 3, c = j & 7;
        cp16(kb + row * 144 + c * 16, src + (size_t)row * 1536 + 1024 + c * 8);
    }
    asm volatile("cp.async.commit_group;");

    {
        const int r   = t >> 1;
        const int seg = t & 1;
        const float* srow = &sS[r * 132 + seg * 64];
        const float* brow = &sB[seg * 64];
        float v[64];
        float m = -1e30f;
        #pragma unroll
        for (int u = 0; u < 16; u++) {
            float4 s4 = *(const float4*)(srow + u * 4);
            float4 b4 = *(const float4*)(brow + u * 4);
            v[u*4+0] = fmaf(s4.x, 0.125f, b4.x);
            v[u*4+1] = fmaf(s4.y, 0.125f, b4.y);
            v[u*4+2] = fmaf(s4.z, 0.125f, b4.z);
            v[u*4+3] = fmaf(s4.w, 0.125f, b4.w);
            m = fmaxf(m, fmaxf(fmaxf(v[u*4], v[u*4+1]), fmaxf(v[u*4+2], v[u*4+3])));
        }
        m = fmaxf(m, __shfl_xor_sync(0xffffffffu, m, 1));
        float s = 0.0f;
        #pragma unroll
        for (int u = 0; u < 64; u++) { v[u] = __expf(v[u] - m); s += v[u]; }
        s += __shfl_xor_sync(0xffffffffu, s, 1);
        const float inv = 1.0f / s;
        __half* prow = sP + r * 264 + seg * 64;
        #pragma unroll
        for (int u = 0; u < 8; u++) {
            __half2 p0 = __floats2half2_rn(v[u*8+0] * inv, v[u*8+1] * inv);
            __half2 p1 = __floats2half2_rn(v[u*8+2] * inv, v[u*8+3] * inv);
            __half2 p2 = __floats2half2_rn(v[u*8+4] * inv, v[u*8+5] * inv);
            __half2 p3 = __floats2half2_rn(v[u*8+6] * inv, v[u*8+7] * inv);
            uint4 pk;
            pk.x = *(uint32_t*)&p0; pk.y = *(uint32_t*)&p1;
            pk.z = *(uint32_t*)&p2; pk.w = *(uint32_t*)&p3;
            *(uint4*)(prow + u * 8) = pk;
        }
    }
    asm volatile("cp.async.wait_group 0;");
    __syncthreads();

    {
        const int r0 = wid * 16;
        wmma::fragment<wmma::accumulator, 16, 16, 16, float> acc[4];
        #pragma unroll
        for (int c = 0; c < 4; c++) wmma::fill_fragment(acc[c], 0.0f);

        #pragma unroll
        for (int j = 0; j < 128; j += 16) {
            wmma::fragment<wmma::matrix_a, 16, 16, 16, __half, wmma::row_major> af;
            wmma::load_matrix_sync(af, &sP[r0 * 264 + j], 264);
            #pragma unroll
            for (int c = 0; c < 4; c++) {
                wmma::fragment<wmma::matrix_b, 16, 16, 16, __half, wmma::row_major> bf;
                wmma::load_matrix_sync(bf, &sV[j * 72 + c * 16], 72);
                wmma::mma_sync(acc[c], af, bf, acc[c]);
            }
        }
        #pragma unroll
        for (int c = 0; c < 4; c++)
            wmma::store_matrix_sync(&sS[r0 * 132 + c * 16], acc[c], 132, wmma::mem_row_major);
    }
    __syncthreads();

    {
        const int r   = t >> 1;
        const int seg = (t & 1) * 32;
        __half* dst = og + (size_t)(b * Lsz + r) * Dsz + h * HDsz + seg;
        const float* srcO = &sS[r * 132 + seg];
        #pragma unroll
        for (int u = 0; u < 4; u++) {
            float4 a = *(const float4*)(srcO + u * 8);
            float4 c = *(const float4*)(srcO + u * 8 + 4);
            __half2 h0 = __floats2half2_rn(a.x, a.y);
            __half2 h1 = __floats2half2_rn(a.z, a.w);
            __half2 h2 = __floats2half2_rn(c.x, c.y);
            __half2 h3 = __floats2half2_rn(c.z, c.w);
            uint4 pk;
            pk.x = *(uint32_t*)&h0; pk.y = *(uint32_t*)&h1;
            pk.z = *(uint32_t*)&h2; pk.w = *(uint32_t*)&h3;
            *(uint4*)(dst + u * 8) = pk;
        }
    }
}

// ---------------------------------------------------------------------------
extern "C" void kernel_launch(void* const* d_in, const int* in_sizes, int n_in,
                              void* d_out, int out_size)
{
    const float* x      = (const float*)d_in[0];
    const float* corr   = (const float*)d_in[1];
    const int*   mask   = (const int*)  d_in[2];
    const float* in_w   = (const float*)d_in[3];
    const float* in_b   = (const float*)d_in[4];
    const float* out_w  = (const float*)d_in[5];
    const float* out_b  = (const float*)d_in[6];
    const float* ln_w   = (const float*)d_in[7];
    const float* ln_b   = (const float*)d_in[8];
    const float* bscale = (const float*)d_in[9];
    float* out = (float*)d_out;

    __half *qkv, *oh, *xh, *wih, *woh;
    cudaGetSymbolAddress((void**)&qkv, g_qkv);
    cudaGetSymbolAddress((void**)&oh,  g_oh);
    cudaGetSymbolAddress((void**)&xh,  g_xh);
    cudaGetSymbolAddress((void**)&wih, g_wih);
    cudaGetSymbolAddress((void**)&woh, g_woh);

    const int M = Bsz * Lsz;   // 65536

    cudaFuncSetAttribute((void*)gemm_qkv,   cudaFuncAttributeMaxDynamicSharedMemorySize, GEMM_SMEM);
    cudaFuncSetAttribute((void*)outproj_ln, cudaFuncAttributeMaxDynamicSharedMemorySize, OPLN_SMEM);
    cudaFuncSetAttribute((void*)attn_kernel, cudaFuncAttributeMaxDynamicSharedMemorySize, ATTN_DYN);

    // 0) fp32 -> fp16 conversions (one launch)
    f2h_multi<<<16896, 256>>>(x, xh, in_w, wih, out_w, woh);

    // 1) QKV projection -> fp16 qkv
    gemm_qkv<<<dim3(3 * Dsz / 128, M / 128), 256, GEMM_SMEM>>>(
        xh, wih, in_b, qkv, M, 3 * Dsz, Dsz);

    // 2) Attention per (b, h)
    attn_kernel<<<Bsz * Hn, 256, ATTN_DYN>>>(qkv, corr, mask, bscale, oh);

    // 3) out_proj + bias + residual + LayerNorm -> out
    outproj_ln<<<M / 64, 512, OPLN_SMEM>>>(oh, woh, out_b, x, ln_w, ln_b, out);
}